// round 1
// baseline (speedup 1.0000x reference)
#include <cuda_runtime.h>

#define BATCH 32
#define SEQ   4096
#define DD    64
#define DK    256

// Scratch (allocation-free rule: __device__ globals)
__device__ float g_Kproj[BATCH * DD * DK];  // [b][d][k]
__device__ float g_Vproj[BATCH * DK * DD];  // [b][k][d]

// ----------------------------------------------------------------------------
// proj_kernel: C[m][n] = sum_t A[t][m] * B[t][n], 64x64 output tile, t=0..4095
//   z=0: A = K[b] (ld 64),           B = E(+kt*64) (ld 256) -> Kproj[b][d][k]
//   z=1: A = F(+kt*64) (ld 256),     B = V[b] (ld 64)       -> Vproj[b][k][d]
// ----------------------------------------------------------------------------
__global__ __launch_bounds__(256)
void proj_kernel(const float* __restrict__ Kin, const float* __restrict__ Vin,
                 const float* __restrict__ Ein, const float* __restrict__ Fin) {
    __shared__ float As[32][64];
    __shared__ float Bs[32][64];

    const int b  = blockIdx.x;
    const int kt = blockIdx.y;
    const int z  = blockIdx.z;

    const float* Ag;
    const float* Bg;
    float* Cg;
    int ldA, ldB, ldC;
    if (z == 0) {
        Ag  = Kin + (size_t)b * SEQ * DD;  ldA = DD;
        Bg  = Ein + kt * 64;               ldB = DK;
        Cg  = g_Kproj + (size_t)b * DD * DK + kt * 64;  ldC = DK;
    } else {
        Ag  = Fin + kt * 64;               ldA = DK;
        Bg  = Vin + (size_t)b * SEQ * DD;  ldB = DD;
        Cg  = g_Vproj + (size_t)b * DK * DD + (size_t)(kt * 64) * DD;  ldC = DD;
    }

    const int tid = threadIdx.x;
    const int tx  = tid & 15;   // output col group (4*tx .. 4*tx+3)
    const int ty  = tid >> 4;   // output row group (4*ty .. 4*ty+3)

    float acc[4][4];
#pragma unroll
    for (int i = 0; i < 4; i++)
#pragma unroll
        for (int j = 0; j < 4; j++) acc[i][j] = 0.0f;

    for (int n0 = 0; n0 < SEQ; n0 += 32) {
        __syncthreads();
#pragma unroll
        for (int v = 0; v < 2; v++) {
            int fi = tid + v * 256;          // float4 index 0..511
            int r  = fi >> 4;                // t-row 0..31
            int c  = fi & 15;                // float4 col 0..15
            *(((float4*)As[r]) + c) =
                *(((const float4*)(Ag + (size_t)(n0 + r) * ldA)) + c);
            *(((float4*)Bs[r]) + c) =
                *(((const float4*)(Bg + (size_t)(n0 + r) * ldB)) + c);
        }
        __syncthreads();

#pragma unroll
        for (int t = 0; t < 32; t++) {
            float4 a4 = *(((float4*)As[t]) + ty);   // broadcast across tx
            float4 b4 = *(((float4*)Bs[t]) + tx);   // contiguous across tx
            float av[4] = {a4.x, a4.y, a4.z, a4.w};
            float bv[4] = {b4.x, b4.y, b4.z, b4.w};
#pragma unroll
            for (int i = 0; i < 4; i++)
#pragma unroll
                for (int j = 0; j < 4; j++) acc[i][j] += av[i] * bv[j];
        }
    }

#pragma unroll
    for (int i = 0; i < 4; i++) {
        float4 o = make_float4(acc[i][0], acc[i][1], acc[i][2], acc[i][3]);
        *((float4*)(Cg + (size_t)(4 * ty + i) * ldC + 4 * tx)) = o;
    }
}

// ----------------------------------------------------------------------------
// attn_kernel: per (batch, 64-row tile):
//   S = Q_tile @ Kproj[b] / 8 ; P = softmax_k(S) ; O = P @ Vproj[b]
// smem: Kp 64KB (reused to hold P) | Vp 64KB | Qs 16KB (transposed [d][row])
// ----------------------------------------------------------------------------
__global__ __launch_bounds__(256, 1)
void attn_kernel(const float* __restrict__ Qin, float* __restrict__ Out) {
    extern __shared__ float sm[];
    float* Kp = sm;                 // [64][256], later P [64 rows][256 k]
    float* Vp = sm + DD * DK;       // [256][64]
    float* Qs = sm + 2 * DD * DK;   // [64 d][64 rows]

    const int b    = blockIdx.x;
    const int row0 = blockIdx.y * 64;
    const int tid  = threadIdx.x;
    const int tx   = tid & 15;
    const int ty   = tid >> 4;

    // Stage Kproj[b] and Vproj[b]
    {
        const float4* Kg = (const float4*)(g_Kproj + (size_t)b * DD * DK);
        float4* Kp4 = (float4*)Kp;
        for (int i = tid; i < DD * DK / 4; i += 256) Kp4[i] = Kg[i];
        const float4* Vg = (const float4*)(g_Vproj + (size_t)b * DK * DD);
        float4* Vp4 = (float4*)Vp;
        for (int i = tid; i < DK * DD / 4; i += 256) Vp4[i] = Vg[i];
    }
    // Stage Q tile transposed: Qs[d][r]
    {
        const float* Qg = Qin + ((size_t)b * SEQ + row0) * DD;
        for (int i = tid; i < 64 * 16; i += 256) {
            int r = i >> 4, c = i & 15;
            float4 q = *((const float4*)(Qg + (size_t)r * DD) + c);
            Qs[(4 * c + 0) * 64 + r] = q.x;
            Qs[(4 * c + 1) * 64 + r] = q.y;
            Qs[(4 * c + 2) * 64 + r] = q.z;
            Qs[(4 * c + 3) * 64 + r] = q.w;
        }
    }
    __syncthreads();

    // ---- GEMM1: S[4 rows][16 k] per thread; thread's k = c*64 + 4*tx + j ----
    float s[4][16];
#pragma unroll
    for (int i = 0; i < 4; i++)
#pragma unroll
        for (int j = 0; j < 16; j++) s[i][j] = 0.0f;

    for (int d = 0; d < DD; d++) {
        float4 q4 = *((float4*)(Qs + d * 64) + ty);     // rows 4ty..4ty+3
        float qa[4] = {q4.x, q4.y, q4.z, q4.w};
#pragma unroll
        for (int c = 0; c < 4; c++) {
            float4 k4 = *((float4*)(Kp + d * DK) + c * 16 + tx);
            float kb[4] = {k4.x, k4.y, k4.z, k4.w};
#pragma unroll
            for (int i = 0; i < 4; i++)
#pragma unroll
                for (int j = 0; j < 4; j++)
                    s[i][c * 4 + j] += qa[i] * kb[j];
        }
    }

    // ---- softmax over k (16 values local x 16 lanes of the tx group) ----
#pragma unroll
    for (int i = 0; i < 4; i++) {
        float m = -1e30f;
#pragma unroll
        for (int j = 0; j < 16; j++) {
            s[i][j] *= 0.125f;                 // 1/sqrt(64)
            m = fmaxf(m, s[i][j]);
        }
#pragma unroll
        for (int o = 8; o >= 1; o >>= 1)
            m = fmaxf(m, __shfl_xor_sync(0xffffffffu, m, o));
        float sum = 0.0f;
#pragma unroll
        for (int j = 0; j < 16; j++) {
            s[i][j] = __expf(s[i][j] - m);
            sum += s[i][j];
        }
#pragma unroll
        for (int o = 8; o >= 1; o >>= 1)
            sum += __shfl_xor_sync(0xffffffffu, sum, o);
        float rs = 1.0f / sum;
#pragma unroll
        for (int j = 0; j < 16; j++) s[i][j] *= rs;
    }

    // ---- write P over Kp (all GEMM1 reads of Kp are done) ----
    __syncthreads();
#pragma unroll
    for (int i = 0; i < 4; i++)
#pragma unroll
        for (int c = 0; c < 4; c++) {
            float4 pv = make_float4(s[i][c * 4 + 0], s[i][c * 4 + 1],
                                    s[i][c * 4 + 2], s[i][c * 4 + 3]);
            *((float4*)(Kp + (size_t)(4 * ty + i) * DK) + c * 16 + tx) = pv;
        }
    __syncthreads();

    // ---- GEMM2: O[4 rows][4 d-cols], reduce over k = 256 ----
    float o[4][4];
#pragma unroll
    for (int i = 0; i < 4; i++)
#pragma unroll
        for (int j = 0; j < 4; j++) o[i][j] = 0.0f;

    for (int k4 = 0; k4 < DK / 4; k4++) {
        float pm[4][4];
#pragma unroll
        for (int i = 0; i < 4; i++) {
            float4 pr = *((float4*)(Kp + (size_t)(4 * ty + i) * DK) + k4);
            pm[i][0] = pr.x; pm[i][1] = pr.y; pm[i][2] = pr.z; pm[i][3] = pr.w;
        }
#pragma unroll
        for (int u = 0; u < 4; u++) {
            float4 v4 = *((float4*)(Vp + (size_t)(k4 * 4 + u) * DD) + tx);
            float vb[4] = {v4.x, v4.y, v4.z, v4.w};
#pragma unroll
            for (int i = 0; i < 4; i++)
#pragma unroll
                for (int j = 0; j < 4; j++)
                    o[i][j] += pm[i][u] * vb[j];
        }
    }

    float* Og = Out + ((size_t)b * SEQ + row0) * DD;
#pragma unroll
    for (int i = 0; i < 4; i++) {
        float4 ov = make_float4(o[i][0], o[i][1], o[i][2], o[i][3]);
        *((float4*)(Og + (size_t)(4 * ty + i) * DD + 4 * tx)) = ov;
    }
}

// ----------------------------------------------------------------------------
extern "C" void kernel_launch(void* const* d_in, const int* in_sizes, int n_in,
                              void* d_out, int out_size) {
    const float* Q = (const float*)d_in[0];
    const float* K = (const float*)d_in[1];
    const float* V = (const float*)d_in[2];
    const float* E = (const float*)d_in[3];
    const float* F = (const float*)d_in[4];
    float* Out = (float*)d_out;

    dim3 g1(BATCH, 4, 2);
    proj_kernel<<<g1, 256>>>(K, V, E, F);

    const int smem = (DD * DK + DK * DD + DD * 64) * (int)sizeof(float);  // 144 KB
    cudaFuncSetAttribute(attn_kernel,
                         cudaFuncAttributeMaxDynamicSharedMemorySize, smem);
    dim3 g2(BATCH, SEQ / 64);
    attn_kernel<<<g2, 256, smem>>>(Q, Out);
}

// round 2
// speedup vs baseline: 1.0056x; 1.0056x over previous
#include <cuda_runtime.h>

#define BATCH 32
#define SEQ   4096
#define DD    64
#define DK    256

// Scratch (allocation-free rule: __device__ globals)
__device__ float g_Kproj[BATCH * DD * DK];  // [b][d][k]
__device__ float g_Vproj[BATCH * DK * DD];  // [b][k][d]

// ----------------------------------------------------------------------------
// proj_kernel: C[m][n] = sum_t A[t][m] * B[t][n], 64x64 output tile, t=0..4095
//   z=0: A = K[b] (ld 64),           B = E(+kt*64) (ld 256) -> Kproj[b][d][k]
//   z=1: A = F(+kt*64) (ld 256),     B = V[b] (ld 64)       -> Vproj[b][k][d]
// ----------------------------------------------------------------------------
__global__ __launch_bounds__(256)
void proj_kernel(const float* __restrict__ Kin, const float* __restrict__ Vin,
                 const float* __restrict__ Ein, const float* __restrict__ Fin) {
    __shared__ float As[32][64];
    __shared__ float Bs[32][64];

    const int b  = blockIdx.x;
    const int kt = blockIdx.y;
    const int z  = blockIdx.z;

    const float* Ag;
    const float* Bg;
    float* Cg;
    int ldA, ldB, ldC;
    if (z == 0) {
        Ag  = Kin + (size_t)b * SEQ * DD;  ldA = DD;
        Bg  = Ein + kt * 64;               ldB = DK;
        Cg  = g_Kproj + (size_t)b * DD * DK + kt * 64;  ldC = DK;
    } else {
        Ag  = Fin + kt * 64;               ldA = DK;
        Bg  = Vin + (size_t)b * SEQ * DD;  ldB = DD;
        Cg  = g_Vproj + (size_t)b * DK * DD + (size_t)(kt * 64) * DD;  ldC = DD;
    }

    const int tid = threadIdx.x;
    const int tx  = tid & 15;   // output col group (4*tx .. 4*tx+3)
    const int ty  = tid >> 4;   // output row group (4*ty .. 4*ty+3)

    float acc[4][4];
#pragma unroll
    for (int i = 0; i < 4; i++)
#pragma unroll
        for (int j = 0; j < 4; j++) acc[i][j] = 0.0f;

    for (int n0 = 0; n0 < SEQ; n0 += 32) {
        __syncthreads();
#pragma unroll
        for (int v = 0; v < 2; v++) {
            int fi = tid + v * 256;          // float4 index 0..511
            int r  = fi >> 4;                // t-row 0..31
            int c  = fi & 15;                // float4 col 0..15
            *(((float4*)As[r]) + c) =
                *(((const float4*)(Ag + (size_t)(n0 + r) * ldA)) + c);
            *(((float4*)Bs[r]) + c) =
                *(((const float4*)(Bg + (size_t)(n0 + r) * ldB)) + c);
        }
        __syncthreads();

#pragma unroll
        for (int t = 0; t < 32; t++) {
            float4 a4 = *(((float4*)As[t]) + ty);   // broadcast across tx
            float4 b4 = *(((float4*)Bs[t]) + tx);   // contiguous across tx
            float av[4] = {a4.x, a4.y, a4.z, a4.w};
            float bv[4] = {b4.x, b4.y, b4.z, b4.w};
#pragma unroll
            for (int i = 0; i < 4; i++)
#pragma unroll
                for (int j = 0; j < 4; j++) acc[i][j] += av[i] * bv[j];
        }
    }

#pragma unroll
    for (int i = 0; i < 4; i++) {
        float4 o = make_float4(acc[i][0], acc[i][1], acc[i][2], acc[i][3]);
        *((float4*)(Cg + (size_t)(4 * ty + i) * ldC + 4 * tx)) = o;
    }
}

// ----------------------------------------------------------------------------
// attn_kernel: per (batch, 64-row tile):
//   S = Q_tile @ Kproj[b] / 8 ; P = softmax_k(S) ; O = P @ Vproj[b]
// smem: Kp 64KB (reused to hold P) | Vp 64KB | Qs 16KB (transposed [d][row])
// ----------------------------------------------------------------------------
__global__ __launch_bounds__(256, 1)
void attn_kernel(const float* __restrict__ Qin, float* __restrict__ Out) {
    extern __shared__ float sm[];
    float* Kp = sm;                 // [64][256], later P [64 rows][256 k]
    float* Vp = sm + DD * DK;       // [256][64]
    float* Qs = sm + 2 * DD * DK;   // [64 d][64 rows]

    const int b    = blockIdx.x;
    const int row0 = blockIdx.y * 64;
    const int tid  = threadIdx.x;
    const int tx   = tid & 15;
    const int ty   = tid >> 4;

    // Stage Kproj[b] and Vproj[b]
    {
        const float4* Kg = (const float4*)(g_Kproj + (size_t)b * DD * DK);
        float4* Kp4 = (float4*)Kp;
        for (int i = tid; i < DD * DK / 4; i += 256) Kp4[i] = Kg[i];
        const float4* Vg = (const float4*)(g_Vproj + (size_t)b * DK * DD);
        float4* Vp4 = (float4*)Vp;
        for (int i = tid; i < DK * DD / 4; i += 256) Vp4[i] = Vg[i];
    }
    // Stage Q tile transposed: Qs[d][r]
    {
        const float* Qg = Qin + ((size_t)b * SEQ + row0) * DD;
        for (int i = tid; i < 64 * 16; i += 256) {
            int r = i >> 4, c = i & 15;
            float4 q = *((const float4*)(Qg + (size_t)r * DD) + c);
            Qs[(4 * c + 0) * 64 + r] = q.x;
            Qs[(4 * c + 1) * 64 + r] = q.y;
            Qs[(4 * c + 2) * 64 + r] = q.z;
            Qs[(4 * c + 3) * 64 + r] = q.w;
        }
    }
    __syncthreads();

    // ---- GEMM1: S[4 rows][16 k] per thread; thread's k = c*64 + 4*tx + j ----
    float s[4][16];
#pragma unroll
    for (int i = 0; i < 4; i++)
#pragma unroll
        for (int j = 0; j < 16; j++) s[i][j] = 0.0f;

    for (int d = 0; d < DD; d++) {
        float4 q4 = *((float4*)(Qs + d * 64) + ty);     // rows 4ty..4ty+3
        float qa[4] = {q4.x, q4.y, q4.z, q4.w};
#pragma unroll
        for (int c = 0; c < 4; c++) {
            float4 k4 = *((float4*)(Kp + d * DK) + c * 16 + tx);
            float kb[4] = {k4.x, k4.y, k4.z, k4.w};
#pragma unroll
            for (int i = 0; i < 4; i++)
#pragma unroll
                for (int j = 0; j < 4; j++)
                    s[i][c * 4 + j] += qa[i] * kb[j];
        }
    }

    // ---- softmax over k (16 values local x 16 lanes of the tx group) ----
#pragma unroll
    for (int i = 0; i < 4; i++) {
        float m = -1e30f;
#pragma unroll
        for (int j = 0; j < 16; j++) {
            s[i][j] *= 0.125f;                 // 1/sqrt(64)
            m = fmaxf(m, s[i][j]);
        }
#pragma unroll
        for (int o = 8; o >= 1; o >>= 1)
            m = fmaxf(m, __shfl_xor_sync(0xffffffffu, m, o));
        float sum = 0.0f;
#pragma unroll
        for (int j = 0; j < 16; j++) {
            s[i][j] = __expf(s[i][j] - m);
            sum += s[i][j];
        }
#pragma unroll
        for (int o = 8; o >= 1; o >>= 1)
            sum += __shfl_xor_sync(0xffffffffu, sum, o);
        float rs = 1.0f / sum;
#pragma unroll
        for (int j = 0; j < 16; j++) s[i][j] *= rs;
    }

    // ---- write P over Kp (all GEMM1 reads of Kp are done) ----
    __syncthreads();
#pragma unroll
    for (int i = 0; i < 4; i++)
#pragma unroll
        for (int c = 0; c < 4; c++) {
            float4 pv = make_float4(s[i][c * 4 + 0], s[i][c * 4 + 1],
                                    s[i][c * 4 + 2], s[i][c * 4 + 3]);
            *((float4*)(Kp + (size_t)(4 * ty + i) * DK) + c * 16 + tx) = pv;
        }
    __syncthreads();

    // ---- GEMM2: O[4 rows][4 d-cols], reduce over k = 256 ----
    float o[4][4];
#pragma unroll
    for (int i = 0; i < 4; i++)
#pragma unroll
        for (int j = 0; j < 4; j++) o[i][j] = 0.0f;

    for (int k4 = 0; k4 < DK / 4; k4++) {
        float pm[4][4];
#pragma unroll
        for (int i = 0; i < 4; i++) {
            float4 pr = *((float4*)(Kp + (size_t)(4 * ty + i) * DK) + k4);
            pm[i][0] = pr.x; pm[i][1] = pr.y; pm[i][2] = pr.z; pm[i][3] = pr.w;
        }
#pragma unroll
        for (int u = 0; u < 4; u++) {
            float4 v4 = *((float4*)(Vp + (size_t)(k4 * 4 + u) * DD) + tx);
            float vb[4] = {v4.x, v4.y, v4.z, v4.w};
#pragma unroll
            for (int i = 0; i < 4; i++)
#pragma unroll
                for (int j = 0; j < 4; j++)
                    o[i][j] += pm[i][u] * vb[j];
        }
    }

    float* Og = Out + ((size_t)b * SEQ + row0) * DD;
#pragma unroll
    for (int i = 0; i < 4; i++) {
        float4 ov = make_float4(o[i][0], o[i][1], o[i][2], o[i][3]);
        *((float4*)(Og + (size_t)(4 * ty + i) * DD + 4 * tx)) = ov;
    }
}

// ----------------------------------------------------------------------------
extern "C" void kernel_launch(void* const* d_in, const int* in_sizes, int n_in,
                              void* d_out, int out_size) {
    const float* Q = (const float*)d_in[0];
    const float* K = (const float*)d_in[1];
    const float* V = (const float*)d_in[2];
    const float* E = (const float*)d_in[3];
    const float* F = (const float*)d_in[4];
    float* Out = (float*)d_out;

    dim3 g1(BATCH, 4, 2);
    proj_kernel<<<g1, 256>>>(K, V, E, F);

    const int smem = (DD * DK + DK * DD + DD * 64) * (int)sizeof(float);  // 144 KB
    cudaFuncSetAttribute(attn_kernel,
                         cudaFuncAttributeMaxDynamicSharedMemorySize, smem);
    dim3 g2(BATCH, SEQ / 64);
    attn_kernel<<<g2, 256, smem>>>(Q, Out);
}

// round 3
// speedup vs baseline: 2.8552x; 2.8395x over previous
#include <cuda_runtime.h>
#include <cuda_bf16.h>
#include <string.h>

#define NB   32
#define NSEQ 4096
#define ND   64
#define NK   256

typedef unsigned u32;
typedef __nv_bfloat16  bf16;
typedef __nv_bfloat162 bf162;

// ---- staging (device globals; allocation-free rule) ----
__device__ bf16 g_Qh[NB*NSEQ*ND], g_Ql[NB*NSEQ*ND];     // Q*0.125 split [b][n][d]
__device__ bf16 g_Kth[NB*ND*NSEQ], g_Ktl[NB*ND*NSEQ];   // K^T split [b][d][n]
__device__ bf16 g_Vth[NB*ND*NSEQ], g_Vtl[NB*ND*NSEQ];   // V^T split [b][d][n]
__device__ bf16 g_Eth[NK*NSEQ],  g_Etl[NK*NSEQ];        // E^T split [k][n]
__device__ bf16 g_Fth[NK*NSEQ],  g_Ftl[NK*NSEQ];        // F^T split [k][n]
__device__ bf16 g_KPh[NB*NK*ND], g_KPl[NB*NK*ND];       // Kproj^T split [b][k][d]
__device__ bf16 g_VPh[NB*ND*NK], g_VPl[NB*ND*NK];       // Vproj^T split [b][d][k]

__device__ __forceinline__ void split2(float x, bf16& h, bf16& l) {
    h = __float2bfloat16_rn(x);
    l = __float2bfloat16_rn(x - __bfloat162float(h));
}
__device__ __forceinline__ u32 b2u(bf162 v) { u32 r; memcpy(&r, &v, 4); return r; }
__device__ __forceinline__ void ldsm4(u32* r, u32 a) {
    asm volatile("ldmatrix.sync.aligned.m8n8.x4.shared.b16 {%0,%1,%2,%3}, [%4];"
        : "=r"(r[0]), "=r"(r[1]), "=r"(r[2]), "=r"(r[3]) : "r"(a));
}
__device__ __forceinline__ void mmabf(float* d, const u32* a, const u32* b) {
    asm volatile("mma.sync.aligned.m16n8k16.row.col.f32.bf16.bf16.f32 "
        "{%0,%1,%2,%3}, {%4,%5,%6,%7}, {%8,%9}, {%0,%1,%2,%3};"
        : "+f"(d[0]), "+f"(d[1]), "+f"(d[2]), "+f"(d[3])
        : "r"(a[0]), "r"(a[1]), "r"(a[2]), "r"(a[3]), "r"(b[0]), "r"(b[1]));
}

// ---------------- conversion kernels ----------------
__global__ __launch_bounds__(256) void convQ(const float* __restrict__ Q) {
    size_t i = (size_t)blockIdx.x * 256 + threadIdx.x;
    float4 v = ((const float4*)Q)[i];
    bf16 h0,h1,h2,h3,l0,l1,l2,l3;
    split2(v.x*0.125f,h0,l0); split2(v.y*0.125f,h1,l1);
    split2(v.z*0.125f,h2,l2); split2(v.w*0.125f,h3,l3);
    bf162* oh = (bf162*)g_Qh; bf162* ol = (bf162*)g_Ql;
    oh[2*i]   = __halves2bfloat162(h0,h1);
    oh[2*i+1] = __halves2bfloat162(h2,h3);
    ol[2*i]   = __halves2bfloat162(l0,l1);
    ol[2*i+1] = __halves2bfloat162(l2,l3);
}

__global__ __launch_bounds__(256) void convKV(const float* __restrict__ Kin,
                                              const float* __restrict__ Vin) {
    __shared__ float S[64][65];
    int b = blockIdx.x, nt = blockIdx.y, mat = blockIdx.z;
    const float* src = (mat ? Vin : Kin) + ((size_t)b*NSEQ + nt*64)*ND;
    bf16* oh = (mat ? g_Vth : g_Kth) + (size_t)b*ND*NSEQ;
    bf16* ol = (mat ? g_Vtl : g_Ktl) + (size_t)b*ND*NSEQ;
    int tid = threadIdx.x;
#pragma unroll
    for (int t = 0; t < 4; t++) {
        int fi = tid + t*256, r = fi>>4, c = fi&15;
        float4 v = ((const float4*)(src + (size_t)r*ND))[c];
        S[r][c*4+0]=v.x; S[r][c*4+1]=v.y; S[r][c*4+2]=v.z; S[r][c*4+3]=v.w;
    }
    __syncthreads();
    int n0 = nt*64;
#pragma unroll
    for (int t = 0; t < 8; t++) {
        int pi = tid + t*256, d = pi>>5, np = pi&31;
        bf16 h0,l0,h1,l1;
        split2(S[2*np][d],h0,l0); split2(S[2*np+1][d],h1,l1);
        size_t o = (size_t)d*NSEQ + n0 + 2*np;
        *(bf162*)(oh+o) = __halves2bfloat162(h0,h1);
        *(bf162*)(ol+o) = __halves2bfloat162(l0,l1);
    }
}

__global__ __launch_bounds__(256) void convEF(const float* __restrict__ Ein,
                                              const float* __restrict__ Fin) {
    __shared__ float S[64][65];
    int nt = blockIdx.x, kt = blockIdx.y, mat = blockIdx.z;
    const float* src = (mat ? Fin : Ein) + (size_t)(nt*64)*NK + kt*64;
    bf16* oh = (mat ? g_Fth : g_Eth);
    bf16* ol = (mat ? g_Ftl : g_Etl);
    int tid = threadIdx.x;
#pragma unroll
    for (int t = 0; t < 4; t++) {
        int fi = tid + t*256, r = fi>>4, c = fi&15;
        float4 v = ((const float4*)(src + (size_t)r*NK))[c];
        S[r][c*4+0]=v.x; S[r][c*4+1]=v.y; S[r][c*4+2]=v.z; S[r][c*4+3]=v.w;
    }
    __syncthreads();
    int n0 = nt*64;
#pragma unroll
    for (int t = 0; t < 8; t++) {
        int pi = tid + t*256, d = pi>>5, np = pi&31;
        bf16 h0,l0,h1,l1;
        split2(S[2*np][d],h0,l0); split2(S[2*np+1][d],h1,l1);
        size_t o = (size_t)(kt*64 + d)*NSEQ + n0 + 2*np;
        *(bf162*)(oh+o) = __halves2bfloat162(h0,h1);
        *(bf162*)(ol+o) = __halves2bfloat162(l0,l1);
    }
}

// -------- proj_mma: C[64m x 64n] = A[64][4096] . B[64][4096]^T (3-term split) --------
// which=0: A=Et rows k -> KP[b][k][d];  which=1: A=Ft rows k -> VP[b][d][k] (transposed store)
__global__ __launch_bounds__(256) void proj_mma() {
    extern __shared__ bf16 smp[];   // A: [2buf][2pol][64][72]; B at +18432 elems
    const int b = blockIdx.x, mbase = blockIdx.y*64, which = blockIdx.z;
    const bf16 *Ah, *Al, *Bh, *Bl;
    if (which == 0) {
        Ah = g_Eth + (size_t)mbase*NSEQ; Al = g_Etl + (size_t)mbase*NSEQ;
        Bh = g_Kth + (size_t)b*ND*NSEQ;  Bl = g_Ktl + (size_t)b*ND*NSEQ;
    } else {
        Ah = g_Fth + (size_t)mbase*NSEQ; Al = g_Ftl + (size_t)mbase*NSEQ;
        Bh = g_Vth + (size_t)b*ND*NSEQ;  Bl = g_Vtl + (size_t)b*ND*NSEQ;
    }
    const int tid = threadIdx.x, lane = tid&31, w = tid>>5;
    const int wm = (w>>1)*16, wn = (w&1)*32;
    const u32 sb = (u32)__cvta_generic_to_shared(smp);

    float acc[4][4];
#pragma unroll
    for (int i = 0; i < 4; i++)
#pragma unroll
        for (int j = 0; j < 4; j++) acc[i][j] = 0.0f;

    uint4 ra[4], rb[4];
#pragma unroll
    for (int t = 0; t < 4; t++) {
        int fi = tid + t*256, pol = fi>>9, rem = fi&511, row = rem>>3, c = rem&7;
        ra[t] = *(const uint4*)((pol?Al:Ah) + (size_t)row*NSEQ + c*8);
        rb[t] = *(const uint4*)((pol?Bl:Bh) + (size_t)row*NSEQ + c*8);
    }
#pragma unroll
    for (int t = 0; t < 4; t++) {
        int fi = tid + t*256, pol = fi>>9, rem = fi&511, row = rem>>3, c = rem&7;
        *(uint4*)(smp + (size_t)(pol*4608 + row*72 + c*8)) = ra[t];
        *(uint4*)(smp + (size_t)(18432 + pol*4608 + row*72 + c*8)) = rb[t];
    }
    __syncthreads();

    const int arow = wm + (lane&7) + ((lane>>3)&1)*8;
    const int acolb = ((lane>>4)&1)*8;
    const int brow_ = (lane&7) + ((lane>>4)&1)*8;
    const int bcolb = ((lane>>3)&1)*8;

    for (int it = 0; it < 64; it++) {
        const int buf = it & 1;
        const bool more = (it+1 < 64);
        if (more) {
            const int k0 = (it+1)*64;
#pragma unroll
            for (int t = 0; t < 4; t++) {
                int fi = tid + t*256, pol = fi>>9, rem = fi&511, row = rem>>3, c = rem&7;
                ra[t] = *(const uint4*)((pol?Al:Ah) + (size_t)row*NSEQ + k0 + c*8);
                rb[t] = *(const uint4*)((pol?Bl:Bh) + (size_t)row*NSEQ + k0 + c*8);
            }
        }
#pragma unroll
        for (int kk = 0; kk < 4; kk++) {
            u32 ah[4], al_[4];
            ldsm4(ah,  sb + (u32)((buf*2+0)*4608 + arow*72 + kk*16 + acolb)*2);
            ldsm4(al_, sb + (u32)((buf*2+1)*4608 + arow*72 + kk*16 + acolb)*2);
#pragma unroll
            for (int p = 0; p < 2; p++) {
                u32 bh[4], bl[4];
                int off = wn + p*16 + brow_;
                ldsm4(bh, sb + (u32)(18432 + (buf*2+0)*4608 + off*72 + kk*16 + bcolb)*2);
                ldsm4(bl, sb + (u32)(18432 + (buf*2+1)*4608 + off*72 + kk*16 + bcolb)*2);
                mmabf(acc[p*2+0], ah,  bh);   mmabf(acc[p*2+1], ah,  bh+2);
                mmabf(acc[p*2+0], ah,  bl);   mmabf(acc[p*2+1], ah,  bl+2);
                mmabf(acc[p*2+0], al_, bh);   mmabf(acc[p*2+1], al_, bh+2);
            }
        }
        if (more) {
            __syncthreads();
            const int nbuf = 1 - buf;
#pragma unroll
            for (int t = 0; t < 4; t++) {
                int fi = tid + t*256, pol = fi>>9, rem = fi&511, row = rem>>3, c = rem&7;
                *(uint4*)(smp + (size_t)((nbuf*2+pol)*4608 + row*72 + c*8)) = ra[t];
                *(uint4*)(smp + (size_t)(18432 + (nbuf*2+pol)*4608 + row*72 + c*8)) = rb[t];
            }
            __syncthreads();
        }
    }

    const int mg = mbase + wm + (lane>>2);
    if (which == 0) {
#pragma unroll
        for (int nt = 0; nt < 4; nt++) {
            int ng = wn + nt*8 + (lane&3)*2;
            bf16 h0,l0,h1,l1;
            split2(acc[nt][0],h0,l0); split2(acc[nt][1],h1,l1);
            size_t o = ((size_t)b*NK + mg)*ND + ng;
            *(bf162*)(g_KPh+o) = __halves2bfloat162(h0,h1);
            *(bf162*)(g_KPl+o) = __halves2bfloat162(l0,l1);
            split2(acc[nt][2],h0,l0); split2(acc[nt][3],h1,l1);
            o = ((size_t)b*NK + mg + 8)*ND + ng;
            *(bf162*)(g_KPh+o) = __halves2bfloat162(h0,h1);
            *(bf162*)(g_KPl+o) = __halves2bfloat162(l0,l1);
        }
    } else {
#pragma unroll
        for (int nt = 0; nt < 4; nt++) {
            int ng = wn + nt*8 + (lane&3)*2;
            bf16 h,l;
            split2(acc[nt][0],h,l);
            g_VPh[((size_t)b*ND+ng)*NK+mg]=h;   g_VPl[((size_t)b*ND+ng)*NK+mg]=l;
            split2(acc[nt][1],h,l);
            g_VPh[((size_t)b*ND+ng+1)*NK+mg]=h; g_VPl[((size_t)b*ND+ng+1)*NK+mg]=l;
            split2(acc[nt][2],h,l);
            g_VPh[((size_t)b*ND+ng)*NK+mg+8]=h;   g_VPl[((size_t)b*ND+ng)*NK+mg+8]=l;
            split2(acc[nt][3],h,l);
            g_VPh[((size_t)b*ND+ng+1)*NK+mg+8]=h; g_VPl[((size_t)b*ND+ng+1)*NK+mg+8]=l;
        }
    }
}

// -------- attn_mma: 128 rows/block; GEMM1 -> softmax -> (repack+GEMM2) --------
// smem bf16 elems: Qs pol*9216 [128][72] | KP 18432+pol*18432 [256][72] | VP 55296+pol*16896 [64][264]
__global__ __launch_bounds__(256, 1) void attn_mma(float* __restrict__ Out) {
    extern __shared__ bf16 sma[];
    const int b = blockIdx.x, row0 = blockIdx.y*128;
    const int tid = threadIdx.x, lane = tid&31, w = tid>>5;
    const u32 sb = (u32)__cvta_generic_to_shared(sma);

    {
        const uint4* qh = (const uint4*)(g_Qh + ((size_t)b*NSEQ + row0)*ND);
        const uint4* ql = (const uint4*)(g_Ql + ((size_t)b*NSEQ + row0)*ND);
#pragma unroll
        for (int t = 0; t < 8; t++) {
            int fi = tid + t*256, pol = fi>>10, rem = fi&1023, r = rem>>3, c = rem&7;
            *(uint4*)(sma + (size_t)(pol*9216 + r*72 + c*8)) = (pol?ql:qh)[r*8+c];
        }
        const uint4* kh = (const uint4*)(g_KPh + (size_t)b*NK*ND);
        const uint4* kl = (const uint4*)(g_KPl + (size_t)b*NK*ND);
#pragma unroll
        for (int t = 0; t < 16; t++) {
            int fi = tid + t*256, pol = fi>>11, rem = fi&2047, r = rem>>3, c = rem&7;
            *(uint4*)(sma + (size_t)(18432 + pol*18432 + r*72 + c*8)) = (pol?kl:kh)[r*8+c];
        }
        const uint4* vh = (const uint4*)(g_VPh + (size_t)b*ND*NK);
        const uint4* vl = (const uint4*)(g_VPl + (size_t)b*ND*NK);
#pragma unroll
        for (int t = 0; t < 16; t++) {
            int fi = tid + t*256, pol = fi>>11, rem = fi&2047, r = rem>>5, c = rem&31;
            *(uint4*)(sma + (size_t)(55296 + pol*16896 + r*264 + c*8)) = (pol?vl:vh)[r*32+c];
        }
    }
    __syncthreads();

    // GEMM1: per warp S[16 x 256]
    u32 qh_[4][4], ql_[4][4];
    {
        int arow = w*16 + (lane&7) + ((lane>>3)&1)*8;
        int acolb = ((lane>>4)&1)*8;
#pragma unroll
        for (int kk = 0; kk < 4; kk++) {
            ldsm4(qh_[kk], sb + (u32)(arow*72 + kk*16 + acolb)*2);
            ldsm4(ql_[kk], sb + (u32)(9216 + arow*72 + kk*16 + acolb)*2);
        }
    }
    float S[32][4];
#pragma unroll
    for (int i = 0; i < 32; i++)
#pragma unroll
        for (int j = 0; j < 4; j++) S[i][j] = 0.0f;

    const int brow_ = (lane&7) + ((lane>>4)&1)*8;
    const int bcolb = ((lane>>3)&1)*8;
#pragma unroll
    for (int p = 0; p < 16; p++) {
#pragma unroll
        for (int kk = 0; kk < 4; kk++) {
            u32 bh[4], bl[4];
            int off = p*16 + brow_;
            ldsm4(bh, sb + (u32)(18432 +         off*72 + kk*16 + bcolb)*2);
            ldsm4(bl, sb + (u32)(18432 + 18432 + off*72 + kk*16 + bcolb)*2);
            mmabf(S[2*p+0], qh_[kk], bh);   mmabf(S[2*p+1], qh_[kk], bh+2);
            mmabf(S[2*p+0], qh_[kk], bl);   mmabf(S[2*p+1], qh_[kk], bl+2);
            mmabf(S[2*p+0], ql_[kk], bh);   mmabf(S[2*p+1], ql_[kk], bh+2);
        }
    }

    // softmax over k=256: rows (lane>>2) [hh=0] and +8 [hh=1]; quad spread over lane&3
#pragma unroll
    for (int hh = 0; hh < 2; hh++) {
        float mx = -1e30f;
#pragma unroll
        for (int nt = 0; nt < 32; nt++)
            mx = fmaxf(mx, fmaxf(S[nt][hh*2], S[nt][hh*2+1]));
        mx = fmaxf(mx, __shfl_xor_sync(0xffffffffu, mx, 1));
        mx = fmaxf(mx, __shfl_xor_sync(0xffffffffu, mx, 2));
        float sum = 0.0f;
#pragma unroll
        for (int nt = 0; nt < 32; nt++) {
            float e0 = __expf(S[nt][hh*2] - mx);
            float e1 = __expf(S[nt][hh*2+1] - mx);
            S[nt][hh*2] = e0; S[nt][hh*2+1] = e1; sum += e0 + e1;
        }
        sum += __shfl_xor_sync(0xffffffffu, sum, 1);
        sum += __shfl_xor_sync(0xffffffffu, sum, 2);
        float rs = 1.0f / sum;
#pragma unroll
        for (int nt = 0; nt < 32; nt++) { S[nt][hh*2] *= rs; S[nt][hh*2+1] *= rs; }
    }

    // GEMM2 with per-k-step repack (D-frag == A-frag layout; zero shuffles)
    float O[8][4];
#pragma unroll
    for (int i = 0; i < 8; i++)
#pragma unroll
        for (int j = 0; j < 4; j++) O[i][j] = 0.0f;

#pragma unroll
    for (int kt = 0; kt < 16; kt++) {
        u32 Ph[4], Pl[4];
#pragma unroll
        for (int j = 0; j < 4; j++) {
            int nt = 2*kt + (j>>1);
            bf16 ha,la,hc,lc;
            split2(S[nt][(j&1)*2],   ha, la);
            split2(S[nt][(j&1)*2+1], hc, lc);
            Ph[j] = b2u(__halves2bfloat162(ha,hc));
            Pl[j] = b2u(__halves2bfloat162(la,lc));
        }
#pragma unroll
        for (int np = 0; np < 4; np++) {
            u32 vh[4], vl[4];
            int off = np*16 + brow_;
            ldsm4(vh, sb + (u32)(55296 +         off*264 + kt*16 + bcolb)*2);
            ldsm4(vl, sb + (u32)(55296 + 16896 + off*264 + kt*16 + bcolb)*2);
            mmabf(O[2*np+0], Ph, vh);   mmabf(O[2*np+1], Ph, vh+2);
            mmabf(O[2*np+0], Ph, vl);   mmabf(O[2*np+1], Ph, vl+2);
            mmabf(O[2*np+0], Pl, vh);   mmabf(O[2*np+1], Pl, vh+2);
        }
    }

    // store fp32 output
    float* Og = Out + ((size_t)b*NSEQ + row0 + w*16 + (lane>>2))*ND;
#pragma unroll
    for (int np = 0; np < 4; np++)
#pragma unroll
        for (int j = 0; j < 2; j++) {
            int d = np*16 + j*8 + (lane&3)*2;
            *(float2*)(Og + d)          = make_float2(O[2*np+j][0], O[2*np+j][1]);
            *(float2*)(Og + 8*ND + d)   = make_float2(O[2*np+j][2], O[2*np+j][3]);
        }
}

// ----------------------------------------------------------------------------
extern "C" void kernel_launch(void* const* d_in, const int* in_sizes, int n_in,
                              void* d_out, int out_size) {
    const float* Q = (const float*)d_in[0];
    const float* K = (const float*)d_in[1];
    const float* V = (const float*)d_in[2];
    const float* E = (const float*)d_in[3];
    const float* F = (const float*)d_in[4];
    float* Out = (float*)d_out;

    convQ<<<NB*NSEQ*ND/4/256, 256>>>(Q);
    convKV<<<dim3(NB, NSEQ/64, 2), 256>>>(K, V);
    convEF<<<dim3(NSEQ/64, NK/64, 2), 256>>>(E, F);

    const int smp = 36864 * 2;   // 73728 B
    cudaFuncSetAttribute(proj_mma, cudaFuncAttributeMaxDynamicSharedMemorySize, smp);
    proj_mma<<<dim3(NB, 4, 2), 256, smp>>>();

    const int sma = 89088 * 2;   // 178176 B
    cudaFuncSetAttribute(attn_mma, cudaFuncAttributeMaxDynamicSharedMemorySize, sma);
    attn_mma<<<dim3(NB, NSEQ/128), 256, sma>>>(Out);
}

// round 4
// speedup vs baseline: 4.5716x; 1.6011x over previous
#include <cuda_runtime.h>
#include <cuda_bf16.h>
#include <string.h>

#define NB   32
#define NSEQ 4096
#define ND   64
#define NK   256

typedef unsigned u32;
typedef __nv_bfloat16  bf16;
typedef __nv_bfloat162 bf162;

// ---- staging (device globals; allocation-free rule) ----
__device__ bf16 g_Kth[NB*ND*NSEQ], g_Ktl[NB*ND*NSEQ];   // K^T split [b][d][n]
__device__ bf16 g_Vth[NB*ND*NSEQ], g_Vtl[NB*ND*NSEQ];   // V^T split [b][d][n]
__device__ bf16 g_Eth[NK*NSEQ],  g_Etl[NK*NSEQ];        // E^T split [k][n]
__device__ bf16 g_Fth[NK*NSEQ],  g_Ftl[NK*NSEQ];        // F^T split [k][n]
__device__ bf16 g_KPh[NB*NK*ND], g_KPl[NB*NK*ND];       // Kproj^T split [b][k][d]
__device__ bf16 g_VPh[NB*ND*NK], g_VPl[NB*ND*NK];       // Vproj^T split [b][d][k]

__device__ __forceinline__ void split2(float x, bf16& h, bf16& l) {
    h = __float2bfloat16_rn(x);
    l = __float2bfloat16_rn(x - __bfloat162float(h));
}
__device__ __forceinline__ u32 b2u(bf162 v) { u32 r; memcpy(&r, &v, 4); return r; }
__device__ __forceinline__ void ldsm4(u32* r, u32 a) {
    asm volatile("ldmatrix.sync.aligned.m8n8.x4.shared.b16 {%0,%1,%2,%3}, [%4];"
        : "=r"(r[0]), "=r"(r[1]), "=r"(r[2]), "=r"(r[3]) : "r"(a));
}
__device__ __forceinline__ void mmabf(float* d, const u32* a, const u32* b) {
    asm volatile("mma.sync.aligned.m16n8k16.row.col.f32.bf16.bf16.f32 "
        "{%0,%1,%2,%3}, {%4,%5,%6,%7}, {%8,%9}, {%0,%1,%2,%3};"
        : "+f"(d[0]), "+f"(d[1]), "+f"(d[2]), "+f"(d[3])
        : "r"(a[0]), "r"(a[1]), "r"(a[2]), "r"(a[3]), "r"(b[0]), "r"(b[1]));
}

// ---------------- conversion kernels ----------------
__global__ __launch_bounds__(256) void convKV(const float* __restrict__ Kin,
                                              const float* __restrict__ Vin) {
    __shared__ float S[64][65];
    int b = blockIdx.x, nt = blockIdx.y, mat = blockIdx.z;
    const float* src = (mat ? Vin : Kin) + ((size_t)b*NSEQ + nt*64)*ND;
    bf16* oh = (mat ? g_Vth : g_Kth) + (size_t)b*ND*NSEQ;
    bf16* ol = (mat ? g_Vtl : g_Ktl) + (size_t)b*ND*NSEQ;
    int tid = threadIdx.x;
#pragma unroll
    for (int t = 0; t < 4; t++) {
        int fi = tid + t*256, r = fi>>4, c = fi&15;
        float4 v = ((const float4*)(src + (size_t)r*ND))[c];
        S[r][c*4+0]=v.x; S[r][c*4+1]=v.y; S[r][c*4+2]=v.z; S[r][c*4+3]=v.w;
    }
    __syncthreads();
    int n0 = nt*64;
#pragma unroll
    for (int t = 0; t < 8; t++) {
        int pi = tid + t*256, d = pi>>5, np = pi&31;
        bf16 h0,l0,h1,l1;
        split2(S[2*np][d],h0,l0); split2(S[2*np+1][d],h1,l1);
        size_t o = (size_t)d*NSEQ + n0 + 2*np;
        *(bf162*)(oh+o) = __halves2bfloat162(h0,h1);
        *(bf162*)(ol+o) = __halves2bfloat162(l0,l1);
    }
}

__global__ __launch_bounds__(256) void convEF(const float* __restrict__ Ein,
                                              const float* __restrict__ Fin) {
    __shared__ float S[64][65];
    int nt = blockIdx.x, kt = blockIdx.y, mat = blockIdx.z;
    const float* src = (mat ? Fin : Ein) + (size_t)(nt*64)*NK + kt*64;
    bf16* oh = (mat ? g_Fth : g_Eth);
    bf16* ol = (mat ? g_Ftl : g_Etl);
    int tid = threadIdx.x;
#pragma unroll
    for (int t = 0; t < 4; t++) {
        int fi = tid + t*256, r = fi>>4, c = fi&15;
        float4 v = ((const float4*)(src + (size_t)r*NK))[c];
        S[r][c*4+0]=v.x; S[r][c*4+1]=v.y; S[r][c*4+2]=v.z; S[r][c*4+3]=v.w;
    }
    __syncthreads();
    int n0 = nt*64;
#pragma unroll
    for (int t = 0; t < 8; t++) {
        int pi = tid + t*256, d = pi>>5, np = pi&31;
        bf16 h0,l0,h1,l1;
        split2(S[2*np][d],h0,l0); split2(S[2*np+1][d],h1,l1);
        size_t o = (size_t)(kt*64 + d)*NSEQ + n0 + 2*np;
        *(bf162*)(oh+o) = __halves2bfloat162(h0,h1);
        *(bf162*)(ol+o) = __halves2bfloat162(l0,l1);
    }
}

// -------- proj_mma: 512 thr / 16 warps, C[128m x 64n], K=4096, 3-term split ----
// which=0: A=Et rows(k) -> KP[b][k][d];  which=1: A=Ft -> VP[b][d][k] (transposed)
// smem bf16: A[buf2][pol2][128][72] = 36864 elems; B at 36864: [buf2][pol2][64][72]
__global__ __launch_bounds__(512) void proj_mma() {
    extern __shared__ bf16 smp[];
    const int b = blockIdx.x, mbase = blockIdx.y*128, which = blockIdx.z;
    const bf16 *Ah, *Al, *Bh, *Bl;
    if (which == 0) {
        Ah = g_Eth + (size_t)mbase*NSEQ; Al = g_Etl + (size_t)mbase*NSEQ;
        Bh = g_Kth + (size_t)b*ND*NSEQ;  Bl = g_Ktl + (size_t)b*ND*NSEQ;
    } else {
        Ah = g_Fth + (size_t)mbase*NSEQ; Al = g_Ftl + (size_t)mbase*NSEQ;
        Bh = g_Vth + (size_t)b*ND*NSEQ;  Bl = g_Vtl + (size_t)b*ND*NSEQ;
    }
    const int tid = threadIdx.x, lane = tid&31, w = tid>>5;
    const int wm = (w>>1)*16, wn = (w&1)*32;
    const u32 sb = (u32)__cvta_generic_to_shared(smp);

    float acc[4][4];
#pragma unroll
    for (int i = 0; i < 4; i++)
#pragma unroll
        for (int j = 0; j < 4; j++) acc[i][j] = 0.0f;

    uint4 ra[4], rb[2];
#pragma unroll
    for (int t = 0; t < 4; t++) {
        int fi = tid + t*512, pol = fi>>10, rem = fi&1023, row = rem>>3, c = rem&7;
        ra[t] = *(const uint4*)((pol?Al:Ah) + (size_t)row*NSEQ + c*8);
    }
#pragma unroll
    for (int t = 0; t < 2; t++) {
        int fi = tid + t*512, pol = fi>>9, rem = fi&511, row = rem>>3, c = rem&7;
        rb[t] = *(const uint4*)((pol?Bl:Bh) + (size_t)row*NSEQ + c*8);
    }
#pragma unroll
    for (int t = 0; t < 4; t++) {
        int fi = tid + t*512, pol = fi>>10, rem = fi&1023, row = rem>>3, c = rem&7;
        *(uint4*)(smp + (size_t)(pol*9216 + row*72 + c*8)) = ra[t];
    }
#pragma unroll
    for (int t = 0; t < 2; t++) {
        int fi = tid + t*512, pol = fi>>9, rem = fi&511, row = rem>>3, c = rem&7;
        *(uint4*)(smp + (size_t)(36864 + pol*4608 + row*72 + c*8)) = rb[t];
    }
    __syncthreads();

    const int arow = wm + (lane&7) + ((lane>>3)&1)*8;
    const int acolb = ((lane>>4)&1)*8;
    const int brow_ = (lane&7) + ((lane>>4)&1)*8;
    const int bcolb = ((lane>>3)&1)*8;

    for (int it = 0; it < 64; it++) {
        const int buf = it & 1;
        const bool more = (it+1 < 64);
        if (more) {
            const int k0 = (it+1)*64;
#pragma unroll
            for (int t = 0; t < 4; t++) {
                int fi = tid + t*512, pol = fi>>10, rem = fi&1023, row = rem>>3, c = rem&7;
                ra[t] = *(const uint4*)((pol?Al:Ah) + (size_t)row*NSEQ + k0 + c*8);
            }
#pragma unroll
            for (int t = 0; t < 2; t++) {
                int fi = tid + t*512, pol = fi>>9, rem = fi&511, row = rem>>3, c = rem&7;
                rb[t] = *(const uint4*)((pol?Bl:Bh) + (size_t)row*NSEQ + k0 + c*8);
            }
        }
#pragma unroll
        for (int kk = 0; kk < 4; kk++) {
            u32 ah[4], al_[4];
            ldsm4(ah,  sb + (u32)((buf*2+0)*9216 + arow*72 + kk*16 + acolb)*2);
            ldsm4(al_, sb + (u32)((buf*2+1)*9216 + arow*72 + kk*16 + acolb)*2);
#pragma unroll
            for (int p = 0; p < 2; p++) {
                u32 bh[4], bl[4];
                int off = wn + p*16 + brow_;
                ldsm4(bh, sb + (u32)(36864 + (buf*2+0)*4608 + off*72 + kk*16 + bcolb)*2);
                ldsm4(bl, sb + (u32)(36864 + (buf*2+1)*4608 + off*72 + kk*16 + bcolb)*2);
                mmabf(acc[p*2+0], ah,  bh);   mmabf(acc[p*2+1], ah,  bh+2);
                mmabf(acc[p*2+0], ah,  bl);   mmabf(acc[p*2+1], ah,  bl+2);
                mmabf(acc[p*2+0], al_, bh);   mmabf(acc[p*2+1], al_, bh+2);
            }
        }
        if (more) {
            __syncthreads();
            const int nbuf = 1 - buf;
#pragma unroll
            for (int t = 0; t < 4; t++) {
                int fi = tid + t*512, pol = fi>>10, rem = fi&1023, row = rem>>3, c = rem&7;
                *(uint4*)(smp + (size_t)((nbuf*2+pol)*9216 + row*72 + c*8)) = ra[t];
            }
#pragma unroll
            for (int t = 0; t < 2; t++) {
                int fi = tid + t*512, pol = fi>>9, rem = fi&511, row = rem>>3, c = rem&7;
                *(uint4*)(smp + (size_t)(36864 + (nbuf*2+pol)*4608 + row*72 + c*8)) = rb[t];
            }
            __syncthreads();
        }
    }

    const int mg = mbase + wm + (lane>>2);
    if (which == 0) {
#pragma unroll
        for (int nt = 0; nt < 4; nt++) {
            int ng = wn + nt*8 + (lane&3)*2;
            bf16 h0,l0,h1,l1;
            split2(acc[nt][0],h0,l0); split2(acc[nt][1],h1,l1);
            size_t o = ((size_t)b*NK + mg)*ND + ng;
            *(bf162*)(g_KPh+o) = __halves2bfloat162(h0,h1);
            *(bf162*)(g_KPl+o) = __halves2bfloat162(l0,l1);
            split2(acc[nt][2],h0,l0); split2(acc[nt][3],h1,l1);
            o = ((size_t)b*NK + mg + 8)*ND + ng;
            *(bf162*)(g_KPh+o) = __halves2bfloat162(h0,h1);
            *(bf162*)(g_KPl+o) = __halves2bfloat162(l0,l1);
        }
    } else {
#pragma unroll
        for (int nt = 0; nt < 4; nt++) {
            int ng = wn + nt*8 + (lane&3)*2;
            bf16 h,l;
            split2(acc[nt][0],h,l);
            g_VPh[((size_t)b*ND+ng)*NK+mg]=h;   g_VPl[((size_t)b*ND+ng)*NK+mg]=l;
            split2(acc[nt][1],h,l);
            g_VPh[((size_t)b*ND+ng+1)*NK+mg]=h; g_VPl[((size_t)b*ND+ng+1)*NK+mg]=l;
            split2(acc[nt][2],h,l);
            g_VPh[((size_t)b*ND+ng)*NK+mg+8]=h;   g_VPl[((size_t)b*ND+ng)*NK+mg+8]=l;
            split2(acc[nt][3],h,l);
            g_VPh[((size_t)b*ND+ng+1)*NK+mg+8]=h; g_VPl[((size_t)b*ND+ng+1)*NK+mg+8]=l;
        }
    }
}

// -------- attn_mma: 128 rows/block; Q frags direct from global fp32 --------
// smem bf16: KP [pol][256][72] (pol*18432) | VP 36864 + [pol][64][264] (pol*16896)
__global__ __launch_bounds__(256, 1) void attn_mma(const float* __restrict__ Qin,
                                                   float* __restrict__ Out) {
    extern __shared__ bf16 sma[];
    const int b = blockIdx.x, row0 = blockIdx.y*128;
    const int tid = threadIdx.x, lane = tid&31, w = tid>>5;
    const u32 sb = (u32)__cvta_generic_to_shared(sma);

    {
        const uint4* kh = (const uint4*)(g_KPh + (size_t)b*NK*ND);
        const uint4* kl = (const uint4*)(g_KPl + (size_t)b*NK*ND);
#pragma unroll
        for (int t = 0; t < 16; t++) {
            int fi = tid + t*256, pol = fi>>11, rem = fi&2047, r = rem>>3, c = rem&7;
            *(uint4*)(sma + (size_t)(pol*18432 + r*72 + c*8)) = (pol?kl:kh)[r*8+c];
        }
        const uint4* vh = (const uint4*)(g_VPh + (size_t)b*ND*NK);
        const uint4* vl = (const uint4*)(g_VPl + (size_t)b*ND*NK);
#pragma unroll
        for (int t = 0; t < 16; t++) {
            int fi = tid + t*256, pol = fi>>11, rem = fi&2047, r = rem>>5, c = rem&31;
            *(uint4*)(sma + (size_t)(36864 + pol*16896 + r*264 + c*8)) = (pol?vl:vh)[r*32+c];
        }
    }

    // Build Q A-frags directly from global fp32 (scale 0.125 folded, split hi/lo)
    u32 qh_[4][4], ql_[4][4];
    {
        const float* Qg = Qin + ((size_t)b*NSEQ + row0 + w*16 + (lane>>2))*ND;
        const int c0 = (lane&3)*2;
#pragma unroll
        for (int kk = 0; kk < 4; kk++) {
#pragma unroll
            for (int j = 0; j < 4; j++) {
                int r_off = (j&1)*8;
                int c_off = kk*16 + c0 + (j>>1)*8;
                float2 v = *(const float2*)(Qg + (size_t)r_off*ND + c_off);
                bf16 h0,l0,h1,l1;
                split2(v.x*0.125f,h0,l0); split2(v.y*0.125f,h1,l1);
                qh_[kk][j] = b2u(__halves2bfloat162(h0,h1));
                ql_[kk][j] = b2u(__halves2bfloat162(l0,l1));
            }
        }
    }
    __syncthreads();

    // GEMM1: per warp S[16 x 256]
    float S[32][4];
#pragma unroll
    for (int i = 0; i < 32; i++)
#pragma unroll
        for (int j = 0; j < 4; j++) S[i][j] = 0.0f;

    const int brow_ = (lane&7) + ((lane>>4)&1)*8;
    const int bcolb = ((lane>>3)&1)*8;
#pragma unroll
    for (int p = 0; p < 16; p++) {
#pragma unroll
        for (int kk = 0; kk < 4; kk++) {
            u32 bh[4], bl[4];
            int off = p*16 + brow_;
            ldsm4(bh, sb + (u32)(        off*72 + kk*16 + bcolb)*2);
            ldsm4(bl, sb + (u32)(18432 + off*72 + kk*16 + bcolb)*2);
            mmabf(S[2*p+0], qh_[kk], bh);   mmabf(S[2*p+1], qh_[kk], bh+2);
            mmabf(S[2*p+0], qh_[kk], bl);   mmabf(S[2*p+1], qh_[kk], bl+2);
            mmabf(S[2*p+0], ql_[kk], bh);   mmabf(S[2*p+1], ql_[kk], bh+2);
        }
    }

    // softmax over k=256
#pragma unroll
    for (int hh = 0; hh < 2; hh++) {
        float mx = -1e30f;
#pragma unroll
        for (int nt = 0; nt < 32; nt++)
            mx = fmaxf(mx, fmaxf(S[nt][hh*2], S[nt][hh*2+1]));
        mx = fmaxf(mx, __shfl_xor_sync(0xffffffffu, mx, 1));
        mx = fmaxf(mx, __shfl_xor_sync(0xffffffffu, mx, 2));
        float sum = 0.0f;
#pragma unroll
        for (int nt = 0; nt < 32; nt++) {
            float e0 = __expf(S[nt][hh*2] - mx);
            float e1 = __expf(S[nt][hh*2+1] - mx);
            S[nt][hh*2] = e0; S[nt][hh*2+1] = e1; sum += e0 + e1;
        }
        sum += __shfl_xor_sync(0xffffffffu, sum, 1);
        sum += __shfl_xor_sync(0xffffffffu, sum, 2);
        float rs = 1.0f / sum;
#pragma unroll
        for (int nt = 0; nt < 32; nt++) { S[nt][hh*2] *= rs; S[nt][hh*2+1] *= rs; }
    }

    // GEMM2 with per-k-step repack (D-frag == A-frag layout)
    float O[8][4];
#pragma unroll
    for (int i = 0; i < 8; i++)
#pragma unroll
        for (int j = 0; j < 4; j++) O[i][j] = 0.0f;

#pragma unroll
    for (int kt = 0; kt < 16; kt++) {
        u32 Ph[4], Pl[4];
#pragma unroll
        for (int j = 0; j < 4; j++) {
            int nt = 2*kt + (j>>1);
            bf16 ha,la,hc,lc;
            split2(S[nt][(j&1)*2],   ha, la);
            split2(S[nt][(j&1)*2+1], hc, lc);
            Ph[j] = b2u(__halves2bfloat162(ha,hc));
            Pl[j] = b2u(__halves2bfloat162(la,lc));
        }
#pragma unroll
        for (int np = 0; np < 4; np++) {
            u32 vh[4], vl[4];
            int off = np*16 + brow_;
            ldsm4(vh, sb + (u32)(36864 +         off*264 + kt*16 + bcolb)*2);
            ldsm4(vl, sb + (u32)(36864 + 16896 + off*264 + kt*16 + bcolb)*2);
            mmabf(O[2*np+0], Ph, vh);   mmabf(O[2*np+1], Ph, vh+2);
            mmabf(O[2*np+0], Ph, vl);   mmabf(O[2*np+1], Ph, vl+2);
            mmabf(O[2*np+0], Pl, vh);   mmabf(O[2*np+1], Pl, vh+2);
        }
    }

    float* Og = Out + ((size_t)b*NSEQ + row0 + w*16 + (lane>>2))*ND;
#pragma unroll
    for (int np = 0; np < 4; np++)
#pragma unroll
        for (int j = 0; j < 2; j++) {
            int d = np*16 + j*8 + (lane&3)*2;
            *(float2*)(Og + d)          = make_float2(O[2*np+j][0], O[2*np+j][1]);
            *(float2*)(Og + 8*ND + d)   = make_float2(O[2*np+j][2], O[2*np+j][3]);
        }
}

// ----------------------------------------------------------------------------
extern "C" void kernel_launch(void* const* d_in, const int* in_sizes, int n_in,
                              void* d_out, int out_size) {
    const float* Q = (const float*)d_in[0];
    const float* K = (const float*)d_in[1];
    const float* V = (const float*)d_in[2];
    const float* E = (const float*)d_in[3];
    const float* F = (const float*)d_in[4];
    float* Out = (float*)d_out;

    convKV<<<dim3(NB, NSEQ/64, 2), 256>>>(K, V);
    convEF<<<dim3(NSEQ/64, NK/64, 2), 256>>>(E, F);

    const int smp = 55296 * 2;   // 110592 B
    cudaFuncSetAttribute(proj_mma, cudaFuncAttributeMaxDynamicSharedMemorySize, smp);
    proj_mma<<<dim3(NB, 2, 2), 512, smp>>>();

    const int sma = 70656 * 2;   // 141312 B
    cudaFuncSetAttribute(attn_mma, cudaFuncAttributeMaxDynamicSharedMemorySize, sma);
    attn_mma<<<dim3(NB, NSEQ/128), 256, sma>>>(Q, Out);
}

// round 5
// speedup vs baseline: 4.9274x; 1.0778x over previous
#include <cuda_runtime.h>
#include <cuda_bf16.h>
#include <string.h>

#define NB   32
#define NSEQ 4096
#define ND   64
#define NK   256

typedef unsigned u32;
typedef __nv_bfloat16  bf16;
typedef __nv_bfloat162 bf162;

// ---- staging (device globals; allocation-free rule) ----
__device__ bf16 g_KPh[NB*NK*ND], g_KPl[NB*NK*ND];       // Kproj^T split [b][k][d]
__device__ bf16 g_VPh[NB*ND*NK], g_VPl[NB*ND*NK];       // Vproj^T split [b][d][k]

__device__ __forceinline__ void split2(float x, bf16& h, bf16& l) {
    h = __float2bfloat16_rn(x);
    l = __float2bfloat16_rn(x - __bfloat162float(h));
}
__device__ __forceinline__ u32 b2u(bf162 v) { u32 r; memcpy(&r, &v, 4); return r; }
__device__ __forceinline__ void ldsm4(u32* r, u32 a) {
    asm volatile("ldmatrix.sync.aligned.m8n8.x4.shared.b16 {%0,%1,%2,%3}, [%4];"
        : "=r"(r[0]), "=r"(r[1]), "=r"(r[2]), "=r"(r[3]) : "r"(a));
}
__device__ __forceinline__ void ldsm4t(u32* r, u32 a) {
    asm volatile("ldmatrix.sync.aligned.m8n8.x4.trans.shared.b16 {%0,%1,%2,%3}, [%4];"
        : "=r"(r[0]), "=r"(r[1]), "=r"(r[2]), "=r"(r[3]) : "r"(a));
}
__device__ __forceinline__ void mmabf(float* d, const u32* a, const u32* b) {
    asm volatile("mma.sync.aligned.m16n8k16.row.col.f32.bf16.bf16.f32 "
        "{%0,%1,%2,%3}, {%4,%5,%6,%7}, {%8,%9}, {%0,%1,%2,%3};"
        : "+f"(d[0]), "+f"(d[1]), "+f"(d[2]), "+f"(d[3])
        : "r"(a[0]), "r"(a[1]), "r"(a[2]), "r"(a[3]), "r"(b[0]), "r"(b[1]));
}
// split a float4 into packed-hi and packed-lo uint2 (4 bf16 each)
__device__ __forceinline__ void split4(float4 v, uint2& hu, uint2& lu) {
    bf16 h0,l0,h1,l1,h2,l2,h3,l3;
    split2(v.x,h0,l0); split2(v.y,h1,l1); split2(v.z,h2,l2); split2(v.w,h3,l3);
    hu.x = b2u(__halves2bfloat162(h0,h1)); hu.y = b2u(__halves2bfloat162(h2,h3));
    lu.x = b2u(__halves2bfloat162(l0,l1)); lu.y = b2u(__halves2bfloat162(l2,l3));
}

// -------- proj_mma (fused conversion): 512 thr / 16 warps, C[128m x 64n], K=4096 --
// which=0: A=E^T rows(k) -> KP[b][k][d];  which=1: A=F^T -> VP[b][d][k] (transposed)
// fp32 tiles loaded in NATURAL layout, split in-register, stored to smem natural:
//   A_nat: [buf2][pol2][64 n][136]  (E/F tile rows n, cols k-local)   base 0
//   B_nat: [buf2][pol2][64 n][72]   (K/V tile rows n, cols d)         base 34816
// fragments via ldmatrix.x4.trans (conflict-free: row strides 272B / 144B)
__global__ __launch_bounds__(512) void proj_mma(const float* __restrict__ Kin,
                                                const float* __restrict__ Vin,
                                                const float* __restrict__ Ein,
                                                const float* __restrict__ Fin) {
    extern __shared__ bf16 smp[];
    const int b = blockIdx.x, mbase = blockIdx.y*128, which = blockIdx.z;
    const float* Ag = (which ? Fin : Ein) + mbase;              // (n,kl): Ag[n*NK+kl]
    const float* Bg = (which ? Vin : Kin) + (size_t)b*NSEQ*ND;  // (n,d):  Bg[n*ND+d]
    const int tid = threadIdx.x, lane = tid&31, w = tid>>5;
    const int wm = (w>>1)*16, wn = (w&1)*32;
    const u32 sb = (u32)__cvta_generic_to_shared(smp);

    float acc[4][4];
#pragma unroll
    for (int i = 0; i < 4; i++)
#pragma unroll
        for (int j = 0; j < 4; j++) acc[i][j] = 0.0f;

    // per-thread staging coords
    const int ar = (tid>>5), ac = (tid&31);   // A: 4 rows apart per t (r = ar + t*16)
    const int br = (tid>>4), bc = (tid&15);   // B: r = br + t*32

    float4 ra[4], rb[2];
#pragma unroll
    for (int t = 0; t < 4; t++)
        ra[t] = *(const float4*)(Ag + (size_t)(ar + t*16)*NK + ac*4);
#pragma unroll
    for (int t = 0; t < 2; t++)
        rb[t] = *(const float4*)(Bg + (size_t)(br + t*32)*ND + bc*4);

#pragma unroll
    for (int t = 0; t < 4; t++) {
        uint2 hu, lu; split4(ra[t], hu, lu);
        int r = ar + t*16;
        *(uint2*)(smp + (size_t)(0*8704 + r*136 + ac*4)) = hu;
        *(uint2*)(smp + (size_t)(1*8704 + r*136 + ac*4)) = lu;
    }
#pragma unroll
    for (int t = 0; t < 2; t++) {
        uint2 hu, lu; split4(rb[t], hu, lu);
        int r = br + t*32;
        *(uint2*)(smp + (size_t)(34816 + 0*4608 + r*72 + bc*4)) = hu;
        *(uint2*)(smp + (size_t)(34816 + 1*4608 + r*72 + bc*4)) = lu;
    }
    __syncthreads();

    // fragment address components (trans ldmatrix)
    const int a_nrow = ((lane>>4)&1)*8 + (lane&7);   // contraction-n row within 16
    const int a_col  = wm + ((lane>>3)&1)*8;          // output k col block
    const int b_nrow = ((lane>>3)&1)*8 + (lane&7);
    const int b_col  = ((lane>>4)&1)*8;

    for (int it = 0; it < 64; it++) {
        const int buf = it & 1;
        const bool more = (it+1 < 64);
        if (more) {
            const int n0 = (it+1)*64;
#pragma unroll
            for (int t = 0; t < 4; t++)
                ra[t] = *(const float4*)(Ag + (size_t)(n0 + ar + t*16)*NK + ac*4);
#pragma unroll
            for (int t = 0; t < 2; t++)
                rb[t] = *(const float4*)(Bg + (size_t)(n0 + br + t*32)*ND + bc*4);
        }
#pragma unroll
        for (int kk = 0; kk < 4; kk++) {
            u32 ah[4], al_[4];
            ldsm4t(ah,  sb + (u32)((buf*2+0)*8704 + (kk*16 + a_nrow)*136 + a_col)*2);
            ldsm4t(al_, sb + (u32)((buf*2+1)*8704 + (kk*16 + a_nrow)*136 + a_col)*2);
#pragma unroll
            for (int p = 0; p < 2; p++) {
                u32 bh[4], bl[4];
                int dc = wn + p*16 + b_col;
                ldsm4t(bh, sb + (u32)(34816 + (buf*2+0)*4608 + (kk*16 + b_nrow)*72 + dc)*2);
                ldsm4t(bl, sb + (u32)(34816 + (buf*2+1)*4608 + (kk*16 + b_nrow)*72 + dc)*2);
                mmabf(acc[p*2+0], ah,  bh);   mmabf(acc[p*2+1], ah,  bh+2);
                mmabf(acc[p*2+0], ah,  bl);   mmabf(acc[p*2+1], ah,  bl+2);
                mmabf(acc[p*2+0], al_, bh);   mmabf(acc[p*2+1], al_, bh+2);
            }
        }
        if (more) {
            __syncthreads();
            const int nbuf = 1 - buf;
#pragma unroll
            for (int t = 0; t < 4; t++) {
                uint2 hu, lu; split4(ra[t], hu, lu);
                int r = ar + t*16;
                *(uint2*)(smp + (size_t)((nbuf*2+0)*8704 + r*136 + ac*4)) = hu;
                *(uint2*)(smp + (size_t)((nbuf*2+1)*8704 + r*136 + ac*4)) = lu;
            }
#pragma unroll
            for (int t = 0; t < 2; t++) {
                uint2 hu, lu; split4(rb[t], hu, lu);
                int r = br + t*32;
                *(uint2*)(smp + (size_t)(34816 + (nbuf*2+0)*4608 + r*72 + bc*4)) = hu;
                *(uint2*)(smp + (size_t)(34816 + (nbuf*2+1)*4608 + r*72 + bc*4)) = lu;
            }
            __syncthreads();
        }
    }

    const int mg = mbase + wm + (lane>>2);
    if (which == 0) {
#pragma unroll
        for (int nt = 0; nt < 4; nt++) {
            int ng = wn + nt*8 + (lane&3)*2;
            bf16 h0,l0,h1,l1;
            split2(acc[nt][0],h0,l0); split2(acc[nt][1],h1,l1);
            size_t o = ((size_t)b*NK + mg)*ND + ng;
            *(bf162*)(g_KPh+o) = __halves2bfloat162(h0,h1);
            *(bf162*)(g_KPl+o) = __halves2bfloat162(l0,l1);
            split2(acc[nt][2],h0,l0); split2(acc[nt][3],h1,l1);
            o = ((size_t)b*NK + mg + 8)*ND + ng;
            *(bf162*)(g_KPh+o) = __halves2bfloat162(h0,h1);
            *(bf162*)(g_KPl+o) = __halves2bfloat162(l0,l1);
        }
    } else {
#pragma unroll
        for (int nt = 0; nt < 4; nt++) {
            int ng = wn + nt*8 + (lane&3)*2;
            bf16 h,l;
            split2(acc[nt][0],h,l);
            g_VPh[((size_t)b*ND+ng)*NK+mg]=h;   g_VPl[((size_t)b*ND+ng)*NK+mg]=l;
            split2(acc[nt][1],h,l);
            g_VPh[((size_t)b*ND+ng+1)*NK+mg]=h; g_VPl[((size_t)b*ND+ng+1)*NK+mg]=l;
            split2(acc[nt][2],h,l);
            g_VPh[((size_t)b*ND+ng)*NK+mg+8]=h;   g_VPl[((size_t)b*ND+ng)*NK+mg+8]=l;
            split2(acc[nt][3],h,l);
            g_VPh[((size_t)b*ND+ng+1)*NK+mg+8]=h; g_VPl[((size_t)b*ND+ng+1)*NK+mg+8]=l;
        }
    }
}

// -------- attn_mma: 128 rows/block; Q frags direct from global fp32 --------
// smem bf16: KP [pol][256][72] (pol*18432) | VP 36864 + [pol][64][264] (pol*16896)
__global__ __launch_bounds__(256, 1) void attn_mma(const float* __restrict__ Qin,
                                                   float* __restrict__ Out) {
    extern __shared__ bf16 sma[];
    const int b = blockIdx.x, row0 = blockIdx.y*128;
    const int tid = threadIdx.x, lane = tid&31, w = tid>>5;
    const u32 sb = (u32)__cvta_generic_to_shared(sma);

    {
        const uint4* kh = (const uint4*)(g_KPh + (size_t)b*NK*ND);
        const uint4* kl = (const uint4*)(g_KPl + (size_t)b*NK*ND);
#pragma unroll
        for (int t = 0; t < 16; t++) {
            int fi = tid + t*256, pol = fi>>11, rem = fi&2047, r = rem>>3, c = rem&7;
            *(uint4*)(sma + (size_t)(pol*18432 + r*72 + c*8)) = (pol?kl:kh)[r*8+c];
        }
        const uint4* vh = (const uint4*)(g_VPh + (size_t)b*ND*NK);
        const uint4* vl = (const uint4*)(g_VPl + (size_t)b*ND*NK);
#pragma unroll
        for (int t = 0; t < 16; t++) {
            int fi = tid + t*256, pol = fi>>11, rem = fi&2047, r = rem>>5, c = rem&31;
            *(uint4*)(sma + (size_t)(36864 + pol*16896 + r*264 + c*8)) = (pol?vl:vh)[r*32+c];
        }
    }

    // Build Q A-frags directly from global fp32 (scale 0.125 folded, split hi/lo)
    u32 qh_[4][4], ql_[4][4];
    {
        const float* Qg = Qin + ((size_t)b*NSEQ + row0 + w*16 + (lane>>2))*ND;
        const int c0 = (lane&3)*2;
#pragma unroll
        for (int kk = 0; kk < 4; kk++) {
#pragma unroll
            for (int j = 0; j < 4; j++) {
                int r_off = (j&1)*8;
                int c_off = kk*16 + c0 + (j>>1)*8;
                float2 v = *(const float2*)(Qg + (size_t)r_off*ND + c_off);
                bf16 h0,l0,h1,l1;
                split2(v.x*0.125f,h0,l0); split2(v.y*0.125f,h1,l1);
                qh_[kk][j] = b2u(__halves2bfloat162(h0,h1));
                ql_[kk][j] = b2u(__halves2bfloat162(l0,l1));
            }
        }
    }
    __syncthreads();

    // GEMM1: per warp S[16 x 256]
    float S[32][4];
#pragma unroll
    for (int i = 0; i < 32; i++)
#pragma unroll
        for (int j = 0; j < 4; j++) S[i][j] = 0.0f;

    const int brow_ = (lane&7) + ((lane>>4)&1)*8;
    const int bcolb = ((lane>>3)&1)*8;
#pragma unroll
    for (int p = 0; p < 16; p++) {
#pragma unroll
        for (int kk = 0; kk < 4; kk++) {
            u32 bh[4], bl[4];
            int off = p*16 + brow_;
            ldsm4(bh, sb + (u32)(        off*72 + kk*16 + bcolb)*2);
            ldsm4(bl, sb + (u32)(18432 + off*72 + kk*16 + bcolb)*2);
            mmabf(S[2*p+0], qh_[kk], bh);   mmabf(S[2*p+1], qh_[kk], bh+2);
            mmabf(S[2*p+0], qh_[kk], bl);   mmabf(S[2*p+1], qh_[kk], bl+2);
            mmabf(S[2*p+0], ql_[kk], bh);   mmabf(S[2*p+1], ql_[kk], bh+2);
        }
    }

    // softmax over k=256
#pragma unroll
    for (int hh = 0; hh < 2; hh++) {
        float mx = -1e30f;
#pragma unroll
        for (int nt = 0; nt < 32; nt++)
            mx = fmaxf(mx, fmaxf(S[nt][hh*2], S[nt][hh*2+1]));
        mx = fmaxf(mx, __shfl_xor_sync(0xffffffffu, mx, 1));
        mx = fmaxf(mx, __shfl_xor_sync(0xffffffffu, mx, 2));
        float sum = 0.0f;
#pragma unroll
        for (int nt = 0; nt < 32; nt++) {
            float e0 = __expf(S[nt][hh*2] - mx);
            float e1 = __expf(S[nt][hh*2+1] - mx);
            S[nt][hh*2] = e0; S[nt][hh*2+1] = e1; sum += e0 + e1;
        }
        sum += __shfl_xor_sync(0xffffffffu, sum, 1);
        sum += __shfl_xor_sync(0xffffffffu, sum, 2);
        float rs = 1.0f / sum;
#pragma unroll
        for (int nt = 0; nt < 32; nt++) { S[nt][hh*2] *= rs; S[nt][hh*2+1] *= rs; }
    }

    // GEMM2 with per-k-step repack (D-frag == A-frag layout)
    float O[8][4];
#pragma unroll
    for (int i = 0; i < 8; i++)
#pragma unroll
        for (int j = 0; j < 4; j++) O[i][j] = 0.0f;

#pragma unroll
    for (int kt = 0; kt < 16; kt++) {
        u32 Ph[4], Pl[4];
#pragma unroll
        for (int j = 0; j < 4; j++) {
            int nt = 2*kt + (j>>1);
            bf16 ha,la,hc,lc;
            split2(S[nt][(j&1)*2],   ha, la);
            split2(S[nt][(j&1)*2+1], hc, lc);
            Ph[j] = b2u(__halves2bfloat162(ha,hc));
            Pl[j] = b2u(__halves2bfloat162(la,lc));
        }
#pragma unroll
        for (int np = 0; np < 4; np++) {
            u32 vh[4], vl[4];
            int off = np*16 + brow_;
            ldsm4(vh, sb + (u32)(36864 +         off*264 + kt*16 + bcolb)*2);
            ldsm4(vl, sb + (u32)(36864 + 16896 + off*264 + kt*16 + bcolb)*2);
            mmabf(O[2*np+0], Ph, vh);   mmabf(O[2*np+1], Ph, vh+2);
            mmabf(O[2*np+0], Ph, vl);   mmabf(O[2*np+1], Ph, vl+2);
            mmabf(O[2*np+0], Pl, vh);   mmabf(O[2*np+1], Pl, vh+2);
        }
    }

    float* Og = Out + ((size_t)b*NSEQ + row0 + w*16 + (lane>>2))*ND;
#pragma unroll
    for (int np = 0; np < 4; np++)
#pragma unroll
        for (int j = 0; j < 2; j++) {
            int d = np*16 + j*8 + (lane&3)*2;
            *(float2*)(Og + d)          = make_float2(O[2*np+j][0], O[2*np+j][1]);
            *(float2*)(Og + 8*ND + d)   = make_float2(O[2*np+j][2], O[2*np+j][3]);
        }
}

// ----------------------------------------------------------------------------
extern "C" void kernel_launch(void* const* d_in, const int* in_sizes, int n_in,
                              void* d_out, int out_size) {
    const float* Q = (const float*)d_in[0];
    const float* K = (const float*)d_in[1];
    const float* V = (const float*)d_in[2];
    const float* E = (const float*)d_in[3];
    const float* F = (const float*)d_in[4];
    float* Out = (float*)d_out;

    const int smp = 53248 * 2;   // 106496 B
    cudaFuncSetAttribute(proj_mma, cudaFuncAttributeMaxDynamicSharedMemorySize, smp);
    proj_mma<<<dim3(NB, 2, 2), 512, smp>>>(K, V, E, F);

    const int sma = 70656 * 2;   // 141312 B
    cudaFuncSetAttribute(attn_mma, cudaFuncAttributeMaxDynamicSharedMemorySize, sma);
    attn_mma<<<dim3(NB, NSEQ/128), 256, sma>>>(Q, Out);
}

// round 6
// speedup vs baseline: 5.0084x; 1.0164x over previous
#include <cuda_runtime.h>
#include <cuda_bf16.h>
#include <string.h>

#define NB   32
#define NSEQ 4096
#define ND   64
#define NK   256

typedef unsigned u32;
typedef __nv_bfloat16  bf16;
typedef __nv_bfloat162 bf162;

// ---- staging (device globals; allocation-free rule) ----
__device__ bf16 g_KPh[NB*NK*ND], g_KPl[NB*NK*ND];       // Kproj^T split [b][k][d]
__device__ bf16 g_VPh[NB*ND*NK], g_VPl[NB*ND*NK];       // Vproj^T split [b][d][k]

__device__ __forceinline__ void split2(float x, bf16& h, bf16& l) {
    h = __float2bfloat16_rn(x);
    l = __float2bfloat16_rn(x - __bfloat162float(h));
}
__device__ __forceinline__ u32 b2u(bf162 v) { u32 r; memcpy(&r, &v, 4); return r; }
__device__ __forceinline__ void ldsm4(u32* r, u32 a) {
    asm volatile("ldmatrix.sync.aligned.m8n8.x4.shared.b16 {%0,%1,%2,%3}, [%4];"
        : "=r"(r[0]), "=r"(r[1]), "=r"(r[2]), "=r"(r[3]) : "r"(a));
}
__device__ __forceinline__ void ldsm4t(u32* r, u32 a) {
    asm volatile("ldmatrix.sync.aligned.m8n8.x4.trans.shared.b16 {%0,%1,%2,%3}, [%4];"
        : "=r"(r[0]), "=r"(r[1]), "=r"(r[2]), "=r"(r[3]) : "r"(a));
}
__device__ __forceinline__ void mmabf(float* d, const u32* a, const u32* b) {
    asm volatile("mma.sync.aligned.m16n8k16.row.col.f32.bf16.bf16.f32 "
        "{%0,%1,%2,%3}, {%4,%5,%6,%7}, {%8,%9}, {%0,%1,%2,%3};"
        : "+f"(d[0]), "+f"(d[1]), "+f"(d[2]), "+f"(d[3])
        : "r"(a[0]), "r"(a[1]), "r"(a[2]), "r"(a[3]), "r"(b[0]), "r"(b[1]));
}
// split a float4 into packed-hi and packed-lo uint2 (4 bf16 each)
__device__ __forceinline__ void split4(float4 v, uint2& hu, uint2& lu) {
    bf16 h0,l0,h1,l1,h2,l2,h3,l3;
    split2(v.x,h0,l0); split2(v.y,h1,l1); split2(v.z,h2,l2); split2(v.w,h3,l3);
    hu.x = b2u(__halves2bfloat162(h0,h1)); hu.y = b2u(__halves2bfloat162(h2,h3));
    lu.x = b2u(__halves2bfloat162(l0,l1)); lu.y = b2u(__halves2bfloat162(l2,l3));
}

// -------- proj_mma (fused conversion): 512 thr / 16 warps, C[128m x 64n], K=4096 --
// which=0: A=E^T rows(k) -> KP[b][k][d];  which=1: A=F^T -> VP[b][d][k] (transposed)
// fp32 tiles loaded NATURAL layout, split in-register, stored to smem natural:
//   A_nat: [buf2][pol2][64 n][136]  base 0;   B_nat: [buf2][pol2][64 n][72] base 34816
// fragments via ldmatrix.x4.trans. SINGLE barrier per iter: store(nbuf) is ordered
// against compute(it-1)'s reads of nbuf by the barrier at the end of it-1.
__global__ __launch_bounds__(512) void proj_mma(const float* __restrict__ Kin,
                                                const float* __restrict__ Vin,
                                                const float* __restrict__ Ein,
                                                const float* __restrict__ Fin) {
    extern __shared__ bf16 smp[];
    const int b = blockIdx.x, mbase = blockIdx.y*128, which = blockIdx.z;
    const float* Ag = (which ? Fin : Ein) + mbase;              // (n,kl): Ag[n*NK+kl]
    const float* Bg = (which ? Vin : Kin) + (size_t)b*NSEQ*ND;  // (n,d):  Bg[n*ND+d]
    const int tid = threadIdx.x, lane = tid&31, w = tid>>5;
    const int wm = (w>>1)*16, wn = (w&1)*32;
    const u32 sb = (u32)__cvta_generic_to_shared(smp);

    float acc[4][4];
#pragma unroll
    for (int i = 0; i < 4; i++)
#pragma unroll
        for (int j = 0; j < 4; j++) acc[i][j] = 0.0f;

    // per-thread staging coords
    const int ar = (tid>>5), ac = (tid&31);   // A: rows ar + t*16
    const int br = (tid>>4), bc = (tid&15);   // B: rows br + t*32

    float4 ra[4], rb[2];
#pragma unroll
    for (int t = 0; t < 4; t++)
        ra[t] = *(const float4*)(Ag + (size_t)(ar + t*16)*NK + ac*4);
#pragma unroll
    for (int t = 0; t < 2; t++)
        rb[t] = *(const float4*)(Bg + (size_t)(br + t*32)*ND + bc*4);

#pragma unroll
    for (int t = 0; t < 4; t++) {
        uint2 hu, lu; split4(ra[t], hu, lu);
        int r = ar + t*16;
        *(uint2*)(smp + (size_t)(0*8704 + r*136 + ac*4)) = hu;
        *(uint2*)(smp + (size_t)(1*8704 + r*136 + ac*4)) = lu;
    }
#pragma unroll
    for (int t = 0; t < 2; t++) {
        uint2 hu, lu; split4(rb[t], hu, lu);
        int r = br + t*32;
        *(uint2*)(smp + (size_t)(34816 + 0*4608 + r*72 + bc*4)) = hu;
        *(uint2*)(smp + (size_t)(34816 + 1*4608 + r*72 + bc*4)) = lu;
    }
    __syncthreads();

    // fragment address components (trans ldmatrix)
    const int a_nrow = ((lane>>4)&1)*8 + (lane&7);   // contraction-n row within 16
    const int a_col  = wm + ((lane>>3)&1)*8;          // output k col block
    const int b_nrow = ((lane>>3)&1)*8 + (lane&7);
    const int b_col  = ((lane>>4)&1)*8;

    for (int it = 0; it < 64; it++) {
        const int buf = it & 1;
        const bool more = (it+1 < 64);
        if (more) {
            const int n0 = (it+1)*64;
#pragma unroll
            for (int t = 0; t < 4; t++)
                ra[t] = *(const float4*)(Ag + (size_t)(n0 + ar + t*16)*NK + ac*4);
#pragma unroll
            for (int t = 0; t < 2; t++)
                rb[t] = *(const float4*)(Bg + (size_t)(n0 + br + t*32)*ND + bc*4);
        }
#pragma unroll
        for (int kk = 0; kk < 4; kk++) {
            u32 ah[4], al_[4];
            ldsm4t(ah,  sb + (u32)((buf*2+0)*8704 + (kk*16 + a_nrow)*136 + a_col)*2);
            ldsm4t(al_, sb + (u32)((buf*2+1)*8704 + (kk*16 + a_nrow)*136 + a_col)*2);
#pragma unroll
            for (int p = 0; p < 2; p++) {
                u32 bh[4], bl[4];
                int dc = wn + p*16 + b_col;
                ldsm4t(bh, sb + (u32)(34816 + (buf*2+0)*4608 + (kk*16 + b_nrow)*72 + dc)*2);
                ldsm4t(bl, sb + (u32)(34816 + (buf*2+1)*4608 + (kk*16 + b_nrow)*72 + dc)*2);
                mmabf(acc[p*2+0], ah,  bh);   mmabf(acc[p*2+1], ah,  bh+2);
                mmabf(acc[p*2+0], ah,  bl);   mmabf(acc[p*2+1], ah,  bl+2);
                mmabf(acc[p*2+0], al_, bh);   mmabf(acc[p*2+1], al_, bh+2);
            }
        }
        if (more) {
            // convert + store into nbuf BEFORE the barrier: overlaps with other
            // warps' MMA work on buf. nbuf writes are safe (its readers finished
            // at the barrier ending iteration it-1).
            const int nbuf = 1 - buf;
#pragma unroll
            for (int t = 0; t < 4; t++) {
                uint2 hu, lu; split4(ra[t], hu, lu);
                int r = ar + t*16;
                *(uint2*)(smp + (size_t)((nbuf*2+0)*8704 + r*136 + ac*4)) = hu;
                *(uint2*)(smp + (size_t)((nbuf*2+1)*8704 + r*136 + ac*4)) = lu;
            }
#pragma unroll
            for (int t = 0; t < 2; t++) {
                uint2 hu, lu; split4(rb[t], hu, lu);
                int r = br + t*32;
                *(uint2*)(smp + (size_t)(34816 + (nbuf*2+0)*4608 + r*72 + bc*4)) = hu;
                *(uint2*)(smp + (size_t)(34816 + (nbuf*2+1)*4608 + r*72 + bc*4)) = lu;
            }
            __syncthreads();   // single barrier per iteration
        }
    }

    const int mg = mbase + wm + (lane>>2);
    if (which == 0) {
#pragma unroll
        for (int nt = 0; nt < 4; nt++) {
            int ng = wn + nt*8 + (lane&3)*2;
            bf16 h0,l0,h1,l1;
            split2(acc[nt][0],h0,l0); split2(acc[nt][1],h1,l1);
            size_t o = ((size_t)b*NK + mg)*ND + ng;
            *(bf162*)(g_KPh+o) = __halves2bfloat162(h0,h1);
            *(bf162*)(g_KPl+o) = __halves2bfloat162(l0,l1);
            split2(acc[nt][2],h0,l0); split2(acc[nt][3],h1,l1);
            o = ((size_t)b*NK + mg + 8)*ND + ng;
            *(bf162*)(g_KPh+o) = __halves2bfloat162(h0,h1);
            *(bf162*)(g_KPl+o) = __halves2bfloat162(l0,l1);
        }
    } else {
#pragma unroll
        for (int nt = 0; nt < 4; nt++) {
            int ng = wn + nt*8 + (lane&3)*2;
            bf16 h,l;
            split2(acc[nt][0],h,l);
            g_VPh[((size_t)b*ND+ng)*NK+mg]=h;   g_VPl[((size_t)b*ND+ng)*NK+mg]=l;
            split2(acc[nt][1],h,l);
            g_VPh[((size_t)b*ND+ng+1)*NK+mg]=h; g_VPl[((size_t)b*ND+ng+1)*NK+mg]=l;
            split2(acc[nt][2],h,l);
            g_VPh[((size_t)b*ND+ng)*NK+mg+8]=h;   g_VPl[((size_t)b*ND+ng)*NK+mg+8]=l;
            split2(acc[nt][3],h,l);
            g_VPh[((size_t)b*ND+ng+1)*NK+mg+8]=h; g_VPl[((size_t)b*ND+ng+1)*NK+mg+8]=l;
        }
    }
}

// -------- attn_mma: 128 rows/block; Q frags direct from global fp32 --------
// smem bf16: KP [pol][256][72] (pol*18432) | VP 36864 + [pol][64][264] (pol*16896)
__global__ __launch_bounds__(256, 1) void attn_mma(const float* __restrict__ Qin,
                                                   float* __restrict__ Out) {
    extern __shared__ bf16 sma[];
    const int b = blockIdx.x, row0 = blockIdx.y*128;
    const int tid = threadIdx.x, lane = tid&31, w = tid>>5;
    const u32 sb = (u32)__cvta_generic_to_shared(sma);

    {
        const uint4* kh = (const uint4*)(g_KPh + (size_t)b*NK*ND);
        const uint4* kl = (const uint4*)(g_KPl + (size_t)b*NK*ND);
#pragma unroll
        for (int t = 0; t < 16; t++) {
            int fi = tid + t*256, pol = fi>>11, rem = fi&2047, r = rem>>3, c = rem&7;
            *(uint4*)(sma + (size_t)(pol*18432 + r*72 + c*8)) = (pol?kl:kh)[r*8+c];
        }
        const uint4* vh = (const uint4*)(g_VPh + (size_t)b*ND*NK);
        const uint4* vl = (const uint4*)(g_VPl + (size_t)b*ND*NK);
#pragma unroll
        for (int t = 0; t < 16; t++) {
            int fi = tid + t*256, pol = fi>>11, rem = fi&2047, r = rem>>5, c = rem&31;
            *(uint4*)(sma + (size_t)(36864 + pol*16896 + r*264 + c*8)) = (pol?vl:vh)[r*32+c];
        }
    }

    // Build Q A-frags directly from global fp32 (scale 0.125 folded, split hi/lo)
    u32 qh_[4][4], ql_[4][4];
    {
        const float* Qg = Qin + ((size_t)b*NSEQ + row0 + w*16 + (lane>>2))*ND;
        const int c0 = (lane&3)*2;
#pragma unroll
        for (int kk = 0; kk < 4; kk++) {
#pragma unroll
            for (int j = 0; j < 4; j++) {
                int r_off = (j&1)*8;
                int c_off = kk*16 + c0 + (j>>1)*8;
                float2 v = *(const float2*)(Qg + (size_t)r_off*ND + c_off);
                bf16 h0,l0,h1,l1;
                split2(v.x*0.125f,h0,l0); split2(v.y*0.125f,h1,l1);
                qh_[kk][j] = b2u(__halves2bfloat162(h0,h1));
                ql_[kk][j] = b2u(__halves2bfloat162(l0,l1));
            }
        }
    }
    __syncthreads();

    // GEMM1: per warp S[16 x 256]
    float S[32][4];
#pragma unroll
    for (int i = 0; i < 32; i++)
#pragma unroll
        for (int j = 0; j < 4; j++) S[i][j] = 0.0f;

    const int brow_ = (lane&7) + ((lane>>4)&1)*8;
    const int bcolb = ((lane>>3)&1)*8;
#pragma unroll
    for (int p = 0; p < 16; p++) {
#pragma unroll
        for (int kk = 0; kk < 4; kk++) {
            u32 bh[4], bl[4];
            int off = p*16 + brow_;
            ldsm4(bh, sb + (u32)(        off*72 + kk*16 + bcolb)*2);
            ldsm4(bl, sb + (u32)(18432 + off*72 + kk*16 + bcolb)*2);
            mmabf(S[2*p+0], qh_[kk], bh);   mmabf(S[2*p+1], qh_[kk], bh+2);
            mmabf(S[2*p+0], qh_[kk], bl);   mmabf(S[2*p+1], qh_[kk], bl+2);
            mmabf(S[2*p+0], ql_[kk], bh);   mmabf(S[2*p+1], ql_[kk], bh+2);
        }
    }

    // softmax over k=256
#pragma unroll
    for (int hh = 0; hh < 2; hh++) {
        float mx = -1e30f;
#pragma unroll
        for (int nt = 0; nt < 32; nt++)
            mx = fmaxf(mx, fmaxf(S[nt][hh*2], S[nt][hh*2+1]));
        mx = fmaxf(mx, __shfl_xor_sync(0xffffffffu, mx, 1));
        mx = fmaxf(mx, __shfl_xor_sync(0xffffffffu, mx, 2));
        float sum = 0.0f;
#pragma unroll
        for (int nt = 0; nt < 32; nt++) {
            float e0 = __expf(S[nt][hh*2] - mx);
            float e1 = __expf(S[nt][hh*2+1] - mx);
            S[nt][hh*2] = e0; S[nt][hh*2+1] = e1; sum += e0 + e1;
        }
        sum += __shfl_xor_sync(0xffffffffu, sum, 1);
        sum += __shfl_xor_sync(0xffffffffu, sum, 2);
        float rs = 1.0f / sum;
#pragma unroll
        for (int nt = 0; nt < 32; nt++) { S[nt][hh*2] *= rs; S[nt][hh*2+1] *= rs; }
    }

    // GEMM2 with per-k-step repack (D-frag == A-frag layout)
    float O[8][4];
#pragma unroll
    for (int i = 0; i < 8; i++)
#pragma unroll
        for (int j = 0; j < 4; j++) O[i][j] = 0.0f;

#pragma unroll
    for (int kt = 0; kt < 16; kt++) {
        u32 Ph[4], Pl[4];
#pragma unroll
        for (int j = 0; j < 4; j++) {
            int nt = 2*kt + (j>>1);
            bf16 ha,la,hc,lc;
            split2(S[nt][(j&1)*2],   ha, la);
            split2(S[nt][(j&1)*2+1], hc, lc);
            Ph[j] = b2u(__halves2bfloat162(ha,hc));
            Pl[j] = b2u(__halves2bfloat162(la,lc));
        }
#pragma unroll
        for (int np = 0; np < 4; np++) {
            u32 vh[4], vl[4];
            int off = np*16 + brow_;
            ldsm4(vh, sb + (u32)(36864 +         off*264 + kt*16 + bcolb)*2);
            ldsm4(vl, sb + (u32)(36864 + 16896 + off*264 + kt*16 + bcolb)*2);
            mmabf(O[2*np+0], Ph, vh);   mmabf(O[2*np+1], Ph, vh+2);
            mmabf(O[2*np+0], Ph, vl);   mmabf(O[2*np+1], Ph, vl+2);
            mmabf(O[2*np+0], Pl, vh);   mmabf(O[2*np+1], Pl, vh+2);
        }
    }

    float* Og = Out + ((size_t)b*NSEQ + row0 + w*16 + (lane>>2))*ND;
#pragma unroll
    for (int np = 0; np < 4; np++)
#pragma unroll
        for (int j = 0; j < 2; j++) {
            int d = np*16 + j*8 + (lane&3)*2;
            *(float2*)(Og + d)          = make_float2(O[2*np+j][0], O[2*np+j][1]);
            *(float2*)(Og + 8*ND + d)   = make_float2(O[2*np+j][2], O[2*np+j][3]);
        }
}

// ----------------------------------------------------------------------------
extern "C" void kernel_launch(void* const* d_in, const int* in_sizes, int n_in,
                              void* d_out, int out_size) {
    const float* Q = (const float*)d_in[0];
    const float* K = (const float*)d_in[1];
    const float* V = (const float*)d_in[2];
    const float* E = (const float*)d_in[3];
    const float* F = (const float*)d_in[4];
    float* Out = (float*)d_out;

    const int smp = 53248 * 2;   // 106496 B
    cudaFuncSetAttribute(proj_mma, cudaFuncAttributeMaxDynamicSharedMemorySize, smp);
    proj_mma<<<dim3(NB, 2, 2), 512, smp>>>(K, V, E, F);

    const int sma = 70656 * 2;   // 141312 B
    cudaFuncSetAttribute(attn_mma, cudaFuncAttributeMaxDynamicSharedMemorySize, sma);
    attn_mma<<<dim3(NB, NSEQ/128), 256, sma>>>(Q, Out);
}

// round 7
// speedup vs baseline: 5.0388x; 1.0061x over previous
#include <cuda_runtime.h>
#include <cuda_bf16.h>
#include <string.h>

#define NB   32
#define NSEQ 4096
#define ND   64
#define NK   256

typedef unsigned u32;
typedef __nv_bfloat16  bf16;
typedef __nv_bfloat162 bf162;

// ---- staging (device globals; allocation-free rule) ----
__device__ bf16 g_Eh[NSEQ*NK], g_El[NSEQ*NK];           // E split, natural [n][k]
__device__ bf16 g_Fh[NSEQ*NK], g_Fl[NSEQ*NK];           // F split, natural [n][k]
__device__ bf16 g_KPh[NB*NK*ND], g_KPl[NB*NK*ND];       // Kproj^T split [b][k][d]
__device__ bf16 g_VPh[NB*ND*NK], g_VPl[NB*ND*NK];       // Vproj^T split [b][d][k]

__device__ __forceinline__ void split2(float x, bf16& h, bf16& l) {
    h = __float2bfloat16_rn(x);
    l = __float2bfloat16_rn(x - __bfloat162float(h));
}
__device__ __forceinline__ u32 b2u(bf162 v) { u32 r; memcpy(&r, &v, 4); return r; }
__device__ __forceinline__ void ldsm4(u32* r, u32 a) {
    asm volatile("ldmatrix.sync.aligned.m8n8.x4.shared.b16 {%0,%1,%2,%3}, [%4];"
        : "=r"(r[0]), "=r"(r[1]), "=r"(r[2]), "=r"(r[3]) : "r"(a));
}
__device__ __forceinline__ void ldsm4t(u32* r, u32 a) {
    asm volatile("ldmatrix.sync.aligned.m8n8.x4.trans.shared.b16 {%0,%1,%2,%3}, [%4];"
        : "=r"(r[0]), "=r"(r[1]), "=r"(r[2]), "=r"(r[3]) : "r"(a));
}
__device__ __forceinline__ void mmabf(float* d, const u32* a, const u32* b) {
    asm volatile("mma.sync.aligned.m16n8k16.row.col.f32.bf16.bf16.f32 "
        "{%0,%1,%2,%3}, {%4,%5,%6,%7}, {%8,%9}, {%0,%1,%2,%3};"
        : "+f"(d[0]), "+f"(d[1]), "+f"(d[2]), "+f"(d[3])
        : "r"(a[0]), "r"(a[1]), "r"(a[2]), "r"(a[3]), "r"(b[0]), "r"(b[1]));
}
// split a float4 into packed-hi and packed-lo uint2 (4 bf16 each)
__device__ __forceinline__ void split4(float4 v, uint2& hu, uint2& lu) {
    bf16 h0,l0,h1,l1,h2,l2,h3,l3;
    split2(v.x,h0,l0); split2(v.y,h1,l1); split2(v.z,h2,l2); split2(v.w,h3,l3);
    hu.x = b2u(__halves2bfloat162(h0,h1)); hu.y = b2u(__halves2bfloat162(h2,h3));
    lu.x = b2u(__halves2bfloat162(l0,l1)); lu.y = b2u(__halves2bfloat162(l2,l3));
}

// -------- convEF: one-shot split of E/F into natural-layout hi/lo bf16 --------
__global__ __launch_bounds__(256) void convEF(const float* __restrict__ Ein,
                                              const float* __restrict__ Fin) {
    const int mat = blockIdx.y;
    size_t i = (size_t)blockIdx.x * 256 + threadIdx.x;       // float4 index
    float4 v = ((const float4*)(mat ? Fin : Ein))[i];
    uint2 hu, lu; split4(v, hu, lu);
    ((uint2*)(mat ? g_Fh : g_Eh))[i] = hu;
    ((uint2*)(mat ? g_Fl : g_El))[i] = lu;
}

// -------- proj_mma: 512 thr / 16 warps, C[128m x 64n], K=4096, 3-term split ----
// which=0: A=E^T rows(k) -> KP[b][k][d];  which=1: A=F^T -> VP[b][d][k] (transposed)
// A (E/F): PRE-SPLIT bf16 loaded natural [n][k] -> plain uint4 copies into smem.
// B (K/V): fp32 loaded natural [n][d], split in-register (fused conversion).
//   A_nat: [buf2][pol2][64 n][136]  base 0;   B_nat: [buf2][pol2][64 n][72] base 34816
// fragments via ldmatrix.x4.trans. Single barrier per iter (double-buffered).
__global__ __launch_bounds__(512) void proj_mma(const float* __restrict__ Kin,
                                                const float* __restrict__ Vin) {
    extern __shared__ bf16 smp[];
    const int b = blockIdx.x, mbase = blockIdx.y*128, which = blockIdx.z;
    const bf16* AgH = (which ? g_Fh : g_Eh) + mbase;            // [n][k-local 0..127]
    const bf16* AgL = (which ? g_Fl : g_El) + mbase;
    const float* Bg = (which ? Vin : Kin) + (size_t)b*NSEQ*ND;  // (n,d)
    const int tid = threadIdx.x, lane = tid&31, w = tid>>5;
    const int wm = (w>>1)*16, wn = (w&1)*32;
    const u32 sb = (u32)__cvta_generic_to_shared(smp);

    float acc[4][4];
#pragma unroll
    for (int i = 0; i < 4; i++)
#pragma unroll
        for (int j = 0; j < 4; j++) acc[i][j] = 0.0f;

    // per-thread staging coords
    const int arow0 = (tid>>4), acol = (tid&15);   // A: uint4 grid 64 x 16, rows arow0 + t*32
    const int br = (tid>>4),  bc = (tid&15);       // B: rows br + t*32, float4 col bc

    uint4 rah[2], ral[2];
    float4 rb[2];
#pragma unroll
    for (int t = 0; t < 2; t++) {
        rah[t] = *(const uint4*)(AgH + (size_t)(arow0 + t*32)*NK + acol*8);
        ral[t] = *(const uint4*)(AgL + (size_t)(arow0 + t*32)*NK + acol*8);
        rb[t]  = *(const float4*)(Bg + (size_t)(br + t*32)*ND + bc*4);
    }
#pragma unroll
    for (int t = 0; t < 2; t++) {
        int r = arow0 + t*32;
        *(uint4*)(smp + (size_t)(0*8704 + r*136 + acol*8)) = rah[t];
        *(uint4*)(smp + (size_t)(1*8704 + r*136 + acol*8)) = ral[t];
        uint2 hu, lu; split4(rb[t], hu, lu);
        int rbr = br + t*32;
        *(uint2*)(smp + (size_t)(34816 + 0*4608 + rbr*72 + bc*4)) = hu;
        *(uint2*)(smp + (size_t)(34816 + 1*4608 + rbr*72 + bc*4)) = lu;
    }
    __syncthreads();

    // fragment address components (trans ldmatrix)
    const int a_nrow = ((lane>>4)&1)*8 + (lane&7);   // contraction-n row within 16
    const int a_col  = wm + ((lane>>3)&1)*8;          // output k col block
    const int b_nrow = ((lane>>3)&1)*8 + (lane&7);
    const int b_col  = ((lane>>4)&1)*8;

    for (int it = 0; it < 64; it++) {
        const int buf = it & 1;
        const bool more = (it+1 < 64);
        if (more) {
            const int n0 = (it+1)*64;
#pragma unroll
            for (int t = 0; t < 2; t++) {
                rah[t] = *(const uint4*)(AgH + (size_t)(n0 + arow0 + t*32)*NK + acol*8);
                ral[t] = *(const uint4*)(AgL + (size_t)(n0 + arow0 + t*32)*NK + acol*8);
                rb[t]  = *(const float4*)(Bg + (size_t)(n0 + br + t*32)*ND + bc*4);
            }
        }
#pragma unroll
        for (int kk = 0; kk < 4; kk++) {
            u32 ah[4], al_[4];
            ldsm4t(ah,  sb + (u32)((buf*2+0)*8704 + (kk*16 + a_nrow)*136 + a_col)*2);
            ldsm4t(al_, sb + (u32)((buf*2+1)*8704 + (kk*16 + a_nrow)*136 + a_col)*2);
#pragma unroll
            for (int p = 0; p < 2; p++) {
                u32 bh[4], bl[4];
                int dc = wn + p*16 + b_col;
                ldsm4t(bh, sb + (u32)(34816 + (buf*2+0)*4608 + (kk*16 + b_nrow)*72 + dc)*2);
                ldsm4t(bl, sb + (u32)(34816 + (buf*2+1)*4608 + (kk*16 + b_nrow)*72 + dc)*2);
                mmabf(acc[p*2+0], ah,  bh);   mmabf(acc[p*2+1], ah,  bh+2);
                mmabf(acc[p*2+0], ah,  bl);   mmabf(acc[p*2+1], ah,  bl+2);
                mmabf(acc[p*2+0], al_, bh);   mmabf(acc[p*2+1], al_, bh+2);
            }
        }
        if (more) {
            const int nbuf = 1 - buf;
#pragma unroll
            for (int t = 0; t < 2; t++) {
                int r = arow0 + t*32;
                *(uint4*)(smp + (size_t)((nbuf*2+0)*8704 + r*136 + acol*8)) = rah[t];
                *(uint4*)(smp + (size_t)((nbuf*2+1)*8704 + r*136 + acol*8)) = ral[t];
                uint2 hu, lu; split4(rb[t], hu, lu);
                int rbr = br + t*32;
                *(uint2*)(smp + (size_t)(34816 + (nbuf*2+0)*4608 + rbr*72 + bc*4)) = hu;
                *(uint2*)(smp + (size_t)(34816 + (nbuf*2+1)*4608 + rbr*72 + bc*4)) = lu;
            }
            __syncthreads();   // single barrier per iteration
        }
    }

    const int mg = mbase + wm + (lane>>2);
    if (which == 0) {
#pragma unroll
        for (int nt = 0; nt < 4; nt++) {
            int ng = wn + nt*8 + (lane&3)*2;
            bf16 h0,l0,h1,l1;
            split2(acc[nt][0],h0,l0); split2(acc[nt][1],h1,l1);
            size_t o = ((size_t)b*NK + mg)*ND + ng;
            *(bf162*)(g_KPh+o) = __halves2bfloat162(h0,h1);
            *(bf162*)(g_KPl+o) = __halves2bfloat162(l0,l1);
            split2(acc[nt][2],h0,l0); split2(acc[nt][3],h1,l1);
            o = ((size_t)b*NK + mg + 8)*ND + ng;
            *(bf162*)(g_KPh+o) = __halves2bfloat162(h0,h1);
            *(bf162*)(g_KPl+o) = __halves2bfloat162(l0,l1);
        }
    } else {
#pragma unroll
        for (int nt = 0; nt < 4; nt++) {
            int ng = wn + nt*8 + (lane&3)*2;
            bf16 h,l;
            split2(acc[nt][0],h,l);
            g_VPh[((size_t)b*ND+ng)*NK+mg]=h;   g_VPl[((size_t)b*ND+ng)*NK+mg]=l;
            split2(acc[nt][1],h,l);
            g_VPh[((size_t)b*ND+ng+1)*NK+mg]=h; g_VPl[((size_t)b*ND+ng+1)*NK+mg]=l;
            split2(acc[nt][2],h,l);
            g_VPh[((size_t)b*ND+ng)*NK+mg+8]=h;   g_VPl[((size_t)b*ND+ng)*NK+mg+8]=l;
            split2(acc[nt][3],h,l);
            g_VPh[((size_t)b*ND+ng+1)*NK+mg+8]=h; g_VPl[((size_t)b*ND+ng+1)*NK+mg+8]=l;
        }
    }
}

// -------- attn_mma: 128 rows/block; Q frags direct from global fp32 --------
// smem bf16: KP [pol][256][72] (pol*18432) | VP 36864 + [pol][64][264] (pol*16896)
__global__ __launch_bounds__(256, 1) void attn_mma(const float* __restrict__ Qin,
                                                   float* __restrict__ Out) {
    extern __shared__ bf16 sma[];
    const int b = blockIdx.x, row0 = blockIdx.y*128;
    const int tid = threadIdx.x, lane = tid&31, w = tid>>5;
    const u32 sb = (u32)__cvta_generic_to_shared(sma);

    {
        const uint4* kh = (const uint4*)(g_KPh + (size_t)b*NK*ND);
        const uint4* kl = (const uint4*)(g_KPl + (size_t)b*NK*ND);
#pragma unroll
        for (int t = 0; t < 16; t++) {
            int fi = tid + t*256, pol = fi>>11, rem = fi&2047, r = rem>>3, c = rem&7;
            *(uint4*)(sma + (size_t)(pol*18432 + r*72 + c*8)) = (pol?kl:kh)[r*8+c];
        }
        const uint4* vh = (const uint4*)(g_VPh + (size_t)b*ND*NK);
        const uint4* vl = (const uint4*)(g_VPl + (size_t)b*ND*NK);
#pragma unroll
        for (int t = 0; t < 16; t++) {
            int fi = tid + t*256, pol = fi>>11, rem = fi&2047, r = rem>>5, c = rem&31;
            *(uint4*)(sma + (size_t)(36864 + pol*16896 + r*264 + c*8)) = (pol?vl:vh)[r*32+c];
        }
    }

    // Build Q A-frags directly from global fp32 (scale 0.125 folded, split hi/lo)
    u32 qh_[4][4], ql_[4][4];
    {
        const float* Qg = Qin + ((size_t)b*NSEQ + row0 + w*16 + (lane>>2))*ND;
        const int c0 = (lane&3)*2;
#pragma unroll
        for (int kk = 0; kk < 4; kk++) {
#pragma unroll
            for (int j = 0; j < 4; j++) {
                int r_off = (j&1)*8;
                int c_off = kk*16 + c0 + (j>>1)*8;
                float2 v = *(const float2*)(Qg + (size_t)r_off*ND + c_off);
                bf16 h0,l0,h1,l1;
                split2(v.x*0.125f,h0,l0); split2(v.y*0.125f,h1,l1);
                qh_[kk][j] = b2u(__halves2bfloat162(h0,h1));
                ql_[kk][j] = b2u(__halves2bfloat162(l0,l1));
            }
        }
    }
    __syncthreads();

    // GEMM1: per warp S[16 x 256]
    float S[32][4];
#pragma unroll
    for (int i = 0; i < 32; i++)
#pragma unroll
        for (int j = 0; j < 4; j++) S[i][j] = 0.0f;

    const int brow_ = (lane&7) + ((lane>>4)&1)*8;
    const int bcolb = ((lane>>3)&1)*8;
#pragma unroll
    for (int p = 0; p < 16; p++) {
#pragma unroll
        for (int kk = 0; kk < 4; kk++) {
            u32 bh[4], bl[4];
            int off = p*16 + brow_;
            ldsm4(bh, sb + (u32)(        off*72 + kk*16 + bcolb)*2);
            ldsm4(bl, sb + (u32)(18432 + off*72 + kk*16 + bcolb)*2);
            mmabf(S[2*p+0], qh_[kk], bh);   mmabf(S[2*p+1], qh_[kk], bh+2);
            mmabf(S[2*p+0], qh_[kk], bl);   mmabf(S[2*p+1], qh_[kk], bl+2);
            mmabf(S[2*p+0], ql_[kk], bh);   mmabf(S[2*p+1], ql_[kk], bh+2);
        }
    }

    // softmax over k=256
#pragma unroll
    for (int hh = 0; hh < 2; hh++) {
        float mx = -1e30f;
#pragma unroll
        for (int nt = 0; nt < 32; nt++)
            mx = fmaxf(mx, fmaxf(S[nt][hh*2], S[nt][hh*2+1]));
        mx = fmaxf(mx, __shfl_xor_sync(0xffffffffu, mx, 1));
        mx = fmaxf(mx, __shfl_xor_sync(0xffffffffu, mx, 2));
        float sum = 0.0f;
#pragma unroll
        for (int nt = 0; nt < 32; nt++) {
            float e0 = __expf(S[nt][hh*2] - mx);
            float e1 = __expf(S[nt][hh*2+1] - mx);
            S[nt][hh*2] = e0; S[nt][hh*2+1] = e1; sum += e0 + e1;
        }
        sum += __shfl_xor_sync(0xffffffffu, sum, 1);
        sum += __shfl_xor_sync(0xffffffffu, sum, 2);
        float rs = 1.0f / sum;
#pragma unroll
        for (int nt = 0; nt < 32; nt++) { S[nt][hh*2] *= rs; S[nt][hh*2+1] *= rs; }
    }

    // GEMM2 with per-k-step repack (D-frag == A-frag layout)
    float O[8][4];
#pragma unroll
    for (int i = 0; i < 8; i++)
#pragma unroll
        for (int j = 0; j < 4; j++) O[i][j] = 0.0f;

#pragma unroll
    for (int kt = 0; kt < 16; kt++) {
        u32 Ph[4], Pl[4];
#pragma unroll
        for (int j = 0; j < 4; j++) {
            int nt = 2*kt + (j>>1);
            bf16 ha,la,hc,lc;
            split2(S[nt][(j&1)*2],   ha, la);
            split2(S[nt][(j&1)*2+1], hc, lc);
            Ph[j] = b2u(__halves2bfloat162(ha,hc));
            Pl[j] = b2u(__halves2bfloat162(la,lc));
        }
#pragma unroll
        for (int np = 0; np < 4; np++) {
            u32 vh[4], vl[4];
            int off = np*16 + brow_;
            ldsm4(vh, sb + (u32)(36864 +         off*264 + kt*16 + bcolb)*2);
            ldsm4(vl, sb + (u32)(36864 + 16896 + off*264 + kt*16 + bcolb)*2);
            mmabf(O[2*np+0], Ph, vh);   mmabf(O[2*np+1], Ph, vh+2);
            mmabf(O[2*np+0], Ph, vl);   mmabf(O[2*np+1], Ph, vl+2);
            mmabf(O[2*np+0], Pl, vh);   mmabf(O[2*np+1], Pl, vh+2);
        }
    }

    float* Og = Out + ((size_t)b*NSEQ + row0 + w*16 + (lane>>2))*ND;
#pragma unroll
    for (int np = 0; np < 4; np++)
#pragma unroll
        for (int j = 0; j < 2; j++) {
            int d = np*16 + j*8 + (lane&3)*2;
            *(float2*)(Og + d)          = make_float2(O[2*np+j][0], O[2*np+j][1]);
            *(float2*)(Og + 8*ND + d)   = make_float2(O[2*np+j][2], O[2*np+j][3]);
        }
}

// ----------------------------------------------------------------------------
extern "C" void kernel_launch(void* const* d_in, const int* in_sizes, int n_in,
                              void* d_out, int out_size) {
    const float* Q = (const float*)d_in[0];
    const float* K = (const float*)d_in[1];
    const float* V = (const float*)d_in[2];
    const float* E = (const float*)d_in[3];
    const float* F = (const float*)d_in[4];
    float* Out = (float*)d_out;

    convEF<<<dim3(NSEQ*NK/4/256, 2), 256>>>(E, F);

    const int smp = 53248 * 2;   // 106496 B
    cudaFuncSetAttribute(proj_mma, cudaFuncAttributeMaxDynamicSharedMemorySize, smp);
    proj_mma<<<dim3(NB, 2, 2), 512, smp>>>(K, V);

    const int sma = 70656 * 2;   // 141312 B
    cudaFuncSetAttribute(attn_mma, cudaFuncAttributeMaxDynamicSharedMemorySize, sma);
    attn_mma<<<dim3(NB, NSEQ/128), 256, sma>>>(Q, Out);
}

// round 9
// speedup vs baseline: 6.8282x; 1.3551x over previous
#include <cuda_runtime.h>
#include <cuda_fp16.h>
#include <string.h>

#define NB   32
#define NSEQ 4096
#define ND   64
#define NK   256

typedef unsigned u32;
typedef __half  f16;
typedef __half2 f162;

// ---- staging (device globals; allocation-free rule) ----
__device__ f16 g_Eh[NSEQ*NK], g_El[NSEQ*NK];   // E split (fp16 hi/lo), natural [n][k]
__device__ f16 g_Fh[NSEQ*NK], g_Fl[NSEQ*NK];   // F split, natural [n][k]
__device__ f16 g_KP[NB*NK*ND];                 // Kproj^T single fp16 [b][k][d]
__device__ f16 g_VP[NB*ND*NK];                 // Vproj^T single fp16 [b][d][k]

__device__ __forceinline__ void split2h(float x, f16& h, f16& l) {
    h = __float2half_rn(x);
    l = __float2half_rn(x - __half2float(h));
}
__device__ __forceinline__ u32 h2u(f162 v) { u32 r; memcpy(&r, &v, 4); return r; }
__device__ __forceinline__ void ldsm4(u32* r, u32 a) {
    asm volatile("ldmatrix.sync.aligned.m8n8.x4.shared.b16 {%0,%1,%2,%3}, [%4];"
        : "=r"(r[0]), "=r"(r[1]), "=r"(r[2]), "=r"(r[3]) : "r"(a));
}
__device__ __forceinline__ void ldsm4t(u32* r, u32 a) {
    asm volatile("ldmatrix.sync.aligned.m8n8.x4.trans.shared.b16 {%0,%1,%2,%3}, [%4];"
        : "=r"(r[0]), "=r"(r[1]), "=r"(r[2]), "=r"(r[3]) : "r"(a));
}
__device__ __forceinline__ void mmah(float* d, const u32* a, const u32* b) {
    asm volatile("mma.sync.aligned.m16n8k16.row.col.f32.f16.f16.f32 "
        "{%0,%1,%2,%3}, {%4,%5,%6,%7}, {%8,%9}, {%0,%1,%2,%3};"
        : "+f"(d[0]), "+f"(d[1]), "+f"(d[2]), "+f"(d[3])
        : "r"(a[0]), "r"(a[1]), "r"(a[2]), "r"(a[3]), "r"(b[0]), "r"(b[1]));
}
// split a float4 into packed-hi and packed-lo uint2 (4 fp16 each)
__device__ __forceinline__ void split4h(float4 v, uint2& hu, uint2& lu) {
    f16 h0,l0,h1,l1,h2,l2,h3,l3;
    split2h(v.x,h0,l0); split2h(v.y,h1,l1); split2h(v.z,h2,l2); split2h(v.w,h3,l3);
    hu.x = h2u(__halves2half2(h0,h1)); hu.y = h2u(__halves2half2(h2,h3));
    lu.x = h2u(__halves2half2(l0,l1)); lu.y = h2u(__halves2half2(l2,l3));
}
// round a float4 to 4 packed fp16 (single precision-level, B side)
__device__ __forceinline__ uint2 cvt4h(float4 v) {
    uint2 r;
    r.x = h2u(__halves2half2(__float2half_rn(v.x), __float2half_rn(v.y)));
    r.y = h2u(__halves2half2(__float2half_rn(v.z), __float2half_rn(v.w)));
    return r;
}

// -------- convEF: one-shot fp16 split of E/F, natural layout [n][k] --------
__global__ __launch_bounds__(256) void convEF(const float* __restrict__ Ein,
                                              const float* __restrict__ Fin) {
    const int mat = blockIdx.y;
    size_t i = (size_t)blockIdx.x * 256 + threadIdx.x;       // float4 index
    float4 v = ((const float4*)(mat ? Fin : Ein))[i];
    uint2 hu, lu; split4h(v, hu, lu);
    ((uint2*)(mat ? g_Fh : g_Eh))[i] = hu;
    ((uint2*)(mat ? g_Fl : g_El))[i] = lu;
}

// -------- proj_mma: 512 thr / 16 warps, C[128m x 64n], K-contraction 4096 ----
// 2-term fp16: A (E/F) = pre-split hi/lo; B (K/V) = single rounded fp16.
// which=0: A=E^T(k rows) -> KP[b][k][d];  which=1: A=F^T -> VP[b][d][k] (transposed)
//   A_nat: [buf2][pol2][64 n][136]  base 0 (34816 halves)
//   B_nat: [buf2][64 n][72]         base 34816 (+buf*4608)
// fragments via ldmatrix.x4.trans. Single barrier per iter (double-buffered).
__global__ __launch_bounds__(512) void proj_mma(const float* __restrict__ Kin,
                                                const float* __restrict__ Vin) {
    extern __shared__ f16 smp[];
    const int b = blockIdx.x, mbase = blockIdx.y*128, which = blockIdx.z;
    const f16* AgH = (which ? g_Fh : g_Eh) + mbase;             // [n][k-local 0..127]
    const f16* AgL = (which ? g_Fl : g_El) + mbase;
    const float* Bg = (which ? Vin : Kin) + (size_t)b*NSEQ*ND;  // (n,d)
    const int tid = threadIdx.x, lane = tid&31, w = tid>>5;
    const int wm = (w>>1)*16, wn = (w&1)*32;
    const u32 sb = (u32)__cvta_generic_to_shared(smp);

    float acc[4][4];
#pragma unroll
    for (int i = 0; i < 4; i++)
#pragma unroll
        for (int j = 0; j < 4; j++) acc[i][j] = 0.0f;

    // per-thread staging coords
    const int arow0 = (tid>>4), acol = (tid&15);   // A: uint4 grid 64 x 16 per pol
    const int br = (tid>>4),  bc = (tid&15);       // B: rows br + t*32, float4 col bc

    uint4 rah[2], ral[2];
    float4 rb[2];
#pragma unroll
    for (int t = 0; t < 2; t++) {
        rah[t] = *(const uint4*)(AgH + (size_t)(arow0 + t*32)*NK + acol*8);
        ral[t] = *(const uint4*)(AgL + (size_t)(arow0 + t*32)*NK + acol*8);
        rb[t]  = *(const float4*)(Bg + (size_t)(br + t*32)*ND + bc*4);
    }
#pragma unroll
    for (int t = 0; t < 2; t++) {
        int r = arow0 + t*32;
        *(uint4*)(smp + (size_t)(0*8704 + r*136 + acol*8)) = rah[t];
        *(uint4*)(smp + (size_t)(1*8704 + r*136 + acol*8)) = ral[t];
        int rbr = br + t*32;
        *(uint2*)(smp + (size_t)(34816 + rbr*72 + bc*4)) = cvt4h(rb[t]);
    }
    __syncthreads();

    // fragment address components (trans ldmatrix)
    const int a_nrow = ((lane>>4)&1)*8 + (lane&7);   // contraction-n row within 16
    const int a_col  = wm + ((lane>>3)&1)*8;          // output k col block
    const int b_nrow = ((lane>>3)&1)*8 + (lane&7);
    const int b_col  = ((lane>>4)&1)*8;

    for (int it = 0; it < 64; it++) {
        const int buf = it & 1;
        const bool more = (it+1 < 64);
        if (more) {
            const int n0 = (it+1)*64;
#pragma unroll
            for (int t = 0; t < 2; t++) {
                rah[t] = *(const uint4*)(AgH + (size_t)(n0 + arow0 + t*32)*NK + acol*8);
                ral[t] = *(const uint4*)(AgL + (size_t)(n0 + arow0 + t*32)*NK + acol*8);
                rb[t]  = *(const float4*)(Bg + (size_t)(n0 + br + t*32)*ND + bc*4);
            }
        }
#pragma unroll
        for (int kk = 0; kk < 4; kk++) {
            u32 ah[4], al_[4];
            ldsm4t(ah,  sb + (u32)((buf*2+0)*8704 + (kk*16 + a_nrow)*136 + a_col)*2);
            ldsm4t(al_, sb + (u32)((buf*2+1)*8704 + (kk*16 + a_nrow)*136 + a_col)*2);
#pragma unroll
            for (int p = 0; p < 2; p++) {
                u32 bh[4];
                int dc = wn + p*16 + b_col;
                ldsm4t(bh, sb + (u32)(34816 + buf*4608 + (kk*16 + b_nrow)*72 + dc)*2);
                mmah(acc[p*2+0], ah,  bh);   mmah(acc[p*2+1], ah,  bh+2);
                mmah(acc[p*2+0], al_, bh);   mmah(acc[p*2+1], al_, bh+2);
            }
        }
        if (more) {
            const int nbuf = 1 - buf;
#pragma unroll
            for (int t = 0; t < 2; t++) {
                int r = arow0 + t*32;
                *(uint4*)(smp + (size_t)((nbuf*2+0)*8704 + r*136 + acol*8)) = rah[t];
                *(uint4*)(smp + (size_t)((nbuf*2+1)*8704 + r*136 + acol*8)) = ral[t];
                int rbr = br + t*32;
                *(uint2*)(smp + (size_t)(34816 + nbuf*4608 + rbr*72 + bc*4)) = cvt4h(rb[t]);
            }
            __syncthreads();   // single barrier per iteration
        }
    }

    // epilogue: round fp32 result to SINGLE fp16 and store
    const int mg = mbase + wm + (lane>>2);
    if (which == 0) {
#pragma unroll
        for (int nt = 0; nt < 4; nt++) {
            int ng = wn + nt*8 + (lane&3)*2;
            size_t o = ((size_t)b*NK + mg)*ND + ng;
            *(f162*)(g_KP + o) = __halves2half2(__float2half_rn(acc[nt][0]),
                                               __float2half_rn(acc[nt][1]));
            o = ((size_t)b*NK + mg + 8)*ND + ng;
            *(f162*)(g_KP + o) = __halves2half2(__float2half_rn(acc[nt][2]),
                                               __float2half_rn(acc[nt][3]));
        }
    } else {
#pragma unroll
        for (int nt = 0; nt < 4; nt++) {
            int ng = wn + nt*8 + (lane&3)*2;
            g_VP[((size_t)b*ND+ng)*NK+mg]     = __float2half_rn(acc[nt][0]);
            g_VP[((size_t)b*ND+ng+1)*NK+mg]   = __float2half_rn(acc[nt][1]);
            g_VP[((size_t)b*ND+ng)*NK+mg+8]   = __float2half_rn(acc[nt][2]);
            g_VP[((size_t)b*ND+ng+1)*NK+mg+8] = __float2half_rn(acc[nt][3]);
        }
    }
}

// -------- attn_mma: 128 rows/block; Q split fp16 in regs, KP/VP single fp16 --
// smem f16: KP [256][72] at 0 (18432) | VP [64][264] at 18432 (16896); 70656 B
__global__ __launch_bounds__(256, 1) void attn_mma(const float* __restrict__ Qin,
                                                   float* __restrict__ Out) {
    extern __shared__ f16 sma[];
    const int b = blockIdx.x, row0 = blockIdx.y*128;
    const int tid = threadIdx.x, lane = tid&31, w = tid>>5;
    const u32 sb = (u32)__cvta_generic_to_shared(sma);

    {
        const uint4* kp = (const uint4*)(g_KP + (size_t)b*NK*ND);
#pragma unroll
        for (int t = 0; t < 8; t++) {
            int i = tid + t*256, r = i>>3, c = i&7;       // 256 rows x 8 uint4
            *(uint4*)(sma + (size_t)(r*72 + c*8)) = kp[r*8 + c];
        }
        const uint4* vp = (const uint4*)(g_VP + (size_t)b*ND*NK);
#pragma unroll
        for (int t = 0; t < 8; t++) {
            int i = tid + t*256, r = i>>5, c = i&31;      // 64 rows x 32 uint4
            *(uint4*)(sma + (size_t)(18432 + r*264 + c*8)) = vp[r*32 + c];
        }
    }

    // Build Q A-frags directly from global fp32 (scale 0.125 folded, fp16 split)
    u32 qh_[4][4], ql_[4][4];
    {
        const float* Qg = Qin + ((size_t)b*NSEQ + row0 + w*16 + (lane>>2))*ND;
        const int c0 = (lane&3)*2;
#pragma unroll
        for (int kk = 0; kk < 4; kk++) {
#pragma unroll
            for (int j = 0; j < 4; j++) {
                int r_off = (j&1)*8;
                int c_off = kk*16 + c0 + (j>>1)*8;
                float2 v = *(const float2*)(Qg + (size_t)r_off*ND + c_off);
                f16 h0,l0,h1,l1;
                split2h(v.x*0.125f,h0,l0); split2h(v.y*0.125f,h1,l1);
                qh_[kk][j] = h2u(__halves2half2(h0,h1));
                ql_[kk][j] = h2u(__halves2half2(l0,l1));
            }
        }
    }
    __syncthreads();

    // GEMM1: per warp S[16 x 256]; 2-term (Q split, KP single)
    float S[32][4];
#pragma unroll
    for (int i = 0; i < 32; i++)
#pragma unroll
        for (int j = 0; j < 4; j++) S[i][j] = 0.0f;

    const int brow_ = (lane&7) + ((lane>>4)&1)*8;
    const int bcolb = ((lane>>3)&1)*8;
#pragma unroll
    for (int p = 0; p < 16; p++) {
#pragma unroll
        for (int kk = 0; kk < 4; kk++) {
            u32 bh[4];
            int off = p*16 + brow_;
            ldsm4(bh, sb + (u32)(off*72 + kk*16 + bcolb)*2);
            mmah(S[2*p+0], qh_[kk], bh);   mmah(S[2*p+1], qh_[kk], bh+2);
            mmah(S[2*p+0], ql_[kk], bh);   mmah(S[2*p+1], ql_[kk], bh+2);
        }
    }

    // softmax over k=256
#pragma unroll
    for (int hh = 0; hh < 2; hh++) {
        float mx = -1e30f;
#pragma unroll
        for (int nt = 0; nt < 32; nt++)
            mx = fmaxf(mx, fmaxf(S[nt][hh*2], S[nt][hh*2+1]));
        mx = fmaxf(mx, __shfl_xor_sync(0xffffffffu, mx, 1));
        mx = fmaxf(mx, __shfl_xor_sync(0xffffffffu, mx, 2));
        float sum = 0.0f;
#pragma unroll
        for (int nt = 0; nt < 32; nt++) {
            float e0 = __expf(S[nt][hh*2] - mx);
            float e1 = __expf(S[nt][hh*2+1] - mx);
            S[nt][hh*2] = e0; S[nt][hh*2+1] = e1; sum += e0 + e1;
        }
        sum += __shfl_xor_sync(0xffffffffu, sum, 1);
        sum += __shfl_xor_sync(0xffffffffu, sum, 2);
        float rs = 1.0f / sum;
#pragma unroll
        for (int nt = 0; nt < 32; nt++) { S[nt][hh*2] *= rs; S[nt][hh*2+1] *= rs; }
    }

    // GEMM2: P split fp16 (per-kt repack; D-frag == A-frag layout), VP single
    float O[8][4];
#pragma unroll
    for (int i = 0; i < 8; i++)
#pragma unroll
        for (int j = 0; j < 4; j++) O[i][j] = 0.0f;

#pragma unroll
    for (int kt = 0; kt < 16; kt++) {
        u32 Ph[4], Pl[4];
#pragma unroll
        for (int j = 0; j < 4; j++) {
            int nt = 2*kt + (j>>1);
            f16 ha,la,hc,lc;
            split2h(S[nt][(j&1)*2],   ha, la);
            split2h(S[nt][(j&1)*2+1], hc, lc);
            Ph[j] = h2u(__halves2half2(ha,hc));
            Pl[j] = h2u(__halves2half2(la,lc));
        }
#pragma unroll
        for (int np = 0; np < 4; np++) {
            u32 vh[4];
            int off = np*16 + brow_;
            ldsm4(vh, sb + (u32)(18432 + off*264 + kt*16 + bcolb)*2);
            mmah(O[2*np+0], Ph, vh);   mmah(O[2*np+1], Ph, vh+2);
            mmah(O[2*np+0], Pl, vh);   mmah(O[2*np+1], Pl, vh+2);
        }
    }

    float* Og = Out + ((size_t)b*NSEQ + row0 + w*16 + (lane>>2))*ND;
#pragma unroll
    for (int np = 0; np < 4; np++)
#pragma unroll
        for (int j = 0; j < 2; j++) {
            int d = np*16 + j*8 + (lane&3)*2;
            *(float2*)(Og + d)          = make_float2(O[2*np+j][0], O[2*np+j][1]);
            *(float2*)(Og + 8*ND + d)   = make_float2(O[2*np+j][2], O[2*np+j][3]);
        }
}

// ----------------------------------------------------------------------------
extern "C" void kernel_launch(void* const* d_in, const int* in_sizes, int n_in,
                              void* d_out, int out_size) {
    const float* Q = (const float*)d_in[0];
    const float* K = (const float*)d_in[1];
    const float* V = (const float*)d_in[2];
    const float* E = (const float*)d_in[3];
    const float* F = (const float*)d_in[4];
    float* Out = (float*)d_out;

    convEF<<<dim3(NSEQ*NK/4/256, 2), 256>>>(E, F);

    const int smp = 44032 * 2;   // 88064 B
    cudaFuncSetAttribute(proj_mma, cudaFuncAttributeMaxDynamicSharedMemorySize, smp);
    proj_mma<<<dim3(NB, 2, 2), 512, smp>>>(K, V);

    const int sma = 35328 * 2;   // 70656 B
    cudaFuncSetAttribute(attn_mma, cudaFuncAttributeMaxDynamicSharedMemorySize, sma);
    attn_mma<<<dim3(NB, NSEQ/128), 256, sma>>>(Q, Out);
}